// round 7
// baseline (speedup 1.0000x reference)
#include <cuda_runtime.h>
#include <cuda_bf16.h>
#include <cstdint>

#define G     64
#define NVOX  (G*G*G)
#define INC   32
#define OUTC  64
#define TZ    16

// ---- device scratch (allocation-free rule: static __device__ arrays) ----
__device__ float g_voxsum[NVOX * INC];   // 32 MB: scatter sums, normalized in place
__device__ float g_cnt[NVOX];            //  1 MB: per-voxel point counts
__device__ float g_conv[NVOX * OUTC];    // 64 MB: conv output (occupancy-masked)

// ---- packed f32x2 helpers (sm_100+ PTX) ----
__device__ __forceinline__ unsigned long long pk2(float a, float b) {
    unsigned long long r;
    asm("mov.b64 %0, {%1, %2};" : "=l"(r) : "f"(a), "f"(b));
    return r;
}
__device__ __forceinline__ void unpk2(unsigned long long v, float& a, float& b) {
    asm("mov.b64 {%0, %1}, %2;" : "=f"(a), "=f"(b) : "l"(v));
}
__device__ __forceinline__ unsigned long long ffma2(unsigned long long a,
                                                    unsigned long long b,
                                                    unsigned long long c) {
    unsigned long long d;
    asm("fma.rn.f32x2 %0, %1, %2, %3;" : "=l"(d) : "l"(a), "l"(b), "l"(c));
    return d;
}

// ============================================================================
// 1) scatter-mean accumulate: per point, vector atomics into its voxel
// ============================================================================
__global__ void scatter_kernel(const float* __restrict__ pts,
                               const float* __restrict__ feats, int n) {
    int i = blockIdx.x * blockDim.x + threadIdx.x;
    if (i >= n) return;
    float px = pts[3 * i + 0];
    float py = pts[3 * i + 1];
    float pz = pts[3 * i + 2];
    int bx = (int)floorf(px);
    int by = (int)floorf(py);
    int bz = (int)floorf(pz);
    bx = min(max(bx, 0), G - 1);
    by = min(max(by, 0), G - 1);
    bz = min(max(bz, 0), G - 1);
    int fl = (bx * G + by) * G + bz;

    atomicAdd(&g_cnt[fl], 1.0f);

    const float4* f4 = (const float4*)(feats + (size_t)i * INC);
    float4* dst = (float4*)(g_voxsum + (size_t)fl * INC);
#pragma unroll
    for (int k = 0; k < INC / 4; k++) {
        float4 v = f4[k];
        atomicAdd(dst + k, v);   // sm_90+ vector red.global.add.v4.f32
    }
}

// ============================================================================
// 2) normalize sums -> means (in place). empty voxels stay exactly 0.
// ============================================================================
__global__ void normalize_kernel() {
    int t = blockIdx.x * blockDim.x + threadIdx.x;   // one float4 per thread
    if (t >= NVOX * (INC / 4)) return;
    int vox = t >> 3;                                // INC/4 == 8
    float c = g_cnt[vox];
    float inv = 1.0f / fmaxf(c, 1.0f);
    float4* p = (float4*)g_voxsum + t;
    float4 v = *p;
    v.x *= inv; v.y *= inv; v.z *= inv; v.w *= inv;
    *p = v;
}

// ============================================================================
// 3) dense 3x3x3 conv, 32 -> 64 channels, SAME padding (zero).
//    R1 data flow, but the z-accumulation now runs on the packed f32x2 pipe:
//    accumulators paired as (z, z+4) so all three dz shifts share the same
//    6 packed operand pairs r2[k] = (r[k], r[k+4]); 12 FFMA2 replace 24 FFMA.
// ============================================================================
__global__ __launch_bounds__(128) void conv_kernel(const float* __restrict__ Wc) {
    __shared__ float sin_[3 * 3 * (TZ + 2) * INC];   // 20736 B

    const int x  = blockIdx.x;
    const int y  = blockIdx.y;
    const int z0 = blockIdx.z * TZ;
    const int t  = threadIdx.x;

    // cooperative halo load with zero padding
    for (int i = t; i < 3 * 3 * (TZ + 2) * INC; i += 128) {
        int ci  = i & (INC - 1);
        int rest = i >> 5;
        int zi  = rest % (TZ + 2); rest /= (TZ + 2);
        int dy  = rest % 3;
        int dx  = rest / 3;
        int gx = x + dx - 1, gy = y + dy - 1, gz = z0 + zi - 1;
        float v = 0.0f;
        if ((unsigned)gx < G && (unsigned)gy < G && (unsigned)gz < G)
            v = g_voxsum[(((size_t)(gx * G + gy) * G + gz) << 5) + ci];
        sin_[i] = v;
    }
    __syncthreads();

    const int co = t & (OUTC - 1);
    const int zb = (t >> 6) * 8;          // 0 or 8

    // acc2[j] holds (z=j, z=j+4), j = 0..3
    unsigned long long acc2[4];
#pragma unroll
    for (int j = 0; j < 4; j++) acc2[j] = pk2(0.0f, 0.0f);

#pragma unroll 1
    for (int dxy = 0; dxy < 9; dxy++) {
        const float* sp = sin_ + dxy * ((TZ + 2) * INC);
        const float* wp = Wc + (size_t)dxy * 3 * INC * OUTC + co;
#pragma unroll
        for (int ci = 0; ci < INC; ci++) {
            float r[10];
#pragma unroll
            for (int j = 0; j < 10; j++) r[j] = sp[(zb + j) * INC + ci];
            unsigned long long r2[6];
#pragma unroll
            for (int k = 0; k < 6; k++) r2[k] = pk2(r[k], r[k + 4]);
#pragma unroll
            for (int dz = 0; dz < 3; dz++) {
                float w = wp[(size_t)(dz * INC + ci) * OUTC];
                unsigned long long w2 = pk2(w, w);
#pragma unroll
                for (int j = 0; j < 4; j++)
                    acc2[j] = ffma2(r2[j + dz], w2, acc2[j]);
            }
        }
    }

    float acc[8];
#pragma unroll
    for (int j = 0; j < 4; j++) unpk2(acc2[j], acc[j], acc[j + 4]);

    int vbase = (x * G + y) * G + z0 + zb;
    size_t obase = (size_t)vbase * OUTC + co;
#pragma unroll
    for (int z = 0; z < 8; z++) {
        float occ = (g_cnt[vbase + z] > 0.0f) ? 1.0f : 0.0f;  // broadcast load
        g_conv[obase + (size_t)z * OUTC] = acc[z] * occ;
    }
}

// ============================================================================
// 4a) residual linear: out = b + feats @ W_lin^T.  (R5 version: measured
//     299us, 48 regs, 56% occ — the f32x2 variant regressed to 353us/100regs.)
//     warp handles (point, half); lane owns co = half*32+lane; W row in 32
//     scalar regs; feats broadcast via shfl.
// ============================================================================
__global__ __launch_bounds__(256) void residual_kernel(const float* __restrict__ feats,
                                                       const float* __restrict__ Wlin,
                                                       const float* __restrict__ blin,
                                                       float* __restrict__ out, int n) {
    const int lane   = threadIdx.x & 31;
    const int gwarp  = (blockIdx.x * blockDim.x + threadIdx.x) >> 5;
    const int nwarps = (gridDim.x * blockDim.x) >> 5;
    const int h      = gwarp & 1;
    const int co     = h * 32 + lane;

    float wreg[INC];
    {
        const float4* r0 = (const float4*)(Wlin + (size_t)co * INC);
#pragma unroll
        for (int k = 0; k < INC / 4; k++) {
            float4 a = r0[k];
            wreg[4 * k + 0] = a.x;
            wreg[4 * k + 1] = a.y;
            wreg[4 * k + 2] = a.z;
            wreg[4 * k + 3] = a.w;
        }
    }
    const float bl = blin[co];

    for (int pair = gwarp; pair < 2 * n; pair += nwarps) {
        int p = pair >> 1;   // h == pair & 1 (nwarps is even)
        float fv = feats[(size_t)p * INC + lane];
        float acc = bl;
#pragma unroll
        for (int ci = 0; ci < INC; ci++) {
            float f = __shfl_sync(0xffffffffu, fv, ci);
            acc += f * wreg[ci];
        }
        out[(size_t)p * OUTC + co] = acc;
    }
}

// ============================================================================
// 4b) trilinear devoxelize: gathers only, accumulating onto the residual
//     already sitting in out. One warp per point, float2 per lane.
// ============================================================================
__global__ __launch_bounds__(256) void devox_kernel(const float* __restrict__ pts,
                                                    float* __restrict__ out, int n) {
    const int lane   = threadIdx.x & 31;
    const int warp   = (blockIdx.x * blockDim.x + threadIdx.x) >> 5;
    const int nwarps = (gridDim.x * blockDim.x) >> 5;

    for (int p = warp; p < n; p += nwarps) {
        float px = pts[3 * p + 0];
        float py = pts[3 * p + 1];
        float pz = pts[3 * p + 2];
        int bx = (int)floorf(px);
        int by = (int)floorf(py);
        int bz = (int)floorf(pz);
        float fx = px - (float)bx;
        float fy = py - (float)by;
        float fz = pz - (float)bz;

        float2* orow = (float2*)out + (size_t)p * (OUTC / 2);
        float2 acc = orow[lane];

#pragma unroll
        for (int c = 0; c < 8; c++) {
            int dx = (c >> 2) & 1, dy = (c >> 1) & 1, dz = c & 1;
            int nx = bx + dx, ny = by + dy, nz = bz + dz;
            float w = (dx ? fx : 1.0f - fx) * (dy ? fy : 1.0f - fy) * (dz ? fz : 1.0f - fz);
            if ((unsigned)nx < G && (unsigned)ny < G && (unsigned)nz < G) {
                int fl = (nx * G + ny) * G + nz;
                const float2* row = (const float2*)(g_conv + (size_t)fl * OUTC);
                float2 v = row[lane];     // occupancy already folded into g_conv
                acc.x += w * v.x;
                acc.y += w * v.y;
            }
        }

        orow[lane] = acc;
    }
}

// ============================================================================
extern "C" void kernel_launch(void* const* d_in, const int* in_sizes, int n_in,
                              void* d_out, int out_size) {
    const float* pts   = (const float*)d_in[0];
    const float* feats = (const float*)d_in[1];
    const float* Wc    = (const float*)d_in[2];
    const float* Wl    = (const float*)d_in[3];
    const float* bl    = (const float*)d_in[4];
    float* out = (float*)d_out;
    int npts = in_sizes[0] / 3;

    void *p_sum = nullptr, *p_cnt = nullptr;
    cudaGetSymbolAddress(&p_sum, g_voxsum);
    cudaGetSymbolAddress(&p_cnt, g_cnt);
    cudaMemsetAsync(p_sum, 0, (size_t)NVOX * INC * sizeof(float));
    cudaMemsetAsync(p_cnt, 0, (size_t)NVOX * sizeof(float));

    scatter_kernel<<<(npts + 255) / 256, 256>>>(pts, feats, npts);

    normalize_kernel<<<(NVOX * (INC / 4) + 255) / 256, 256>>>();

    dim3 cgrid(G, G, G / TZ);
    conv_kernel<<<cgrid, 128>>>(Wc);

    residual_kernel<<<2048, 256>>>(feats, Wl, bl, out, npts);

    devox_kernel<<<4096, 256>>>(pts, out, npts);
}

// round 8
// speedup vs baseline: 1.7126x; 1.7126x over previous
#include <cuda_runtime.h>
#include <cuda_bf16.h>
#include <cstdint>

#define G     64
#define NVOX  (G*G*G)
#define INC   32
#define OUTC  64
#define PANE_ROWS   66
#define PANE_STRIDE 36   // words; 36 mod 32 = 4 -> frag LDS bank-conflict-free

// ---- device scratch (allocation-free rule: static __device__ arrays) ----
__device__ float g_voxsum[NVOX * INC];        // 32 MB: scatter sums -> means
__device__ float g_cnt[NVOX];                 //  1 MB: per-voxel point counts
__device__ float g_conv[NVOX * OUTC];         // 64 MB: conv output (occ-masked)
__device__ float g_wfrag[27 * 4 * 8 * 32 * 2]; // W_conv in mma B-fragment order (tf32)

__device__ __forceinline__ unsigned cvt_tf32(float f) {
    unsigned u;
    asm("cvt.rna.tf32.f32 %0, %1;" : "=r"(u) : "f"(f));
    return u;
}

__device__ __forceinline__ void mma_tf32(float c[4], unsigned a0, unsigned a1,
                                         unsigned a2, unsigned a3,
                                         unsigned b0, unsigned b1) {
    asm volatile(
        "mma.sync.aligned.m16n8k8.row.col.f32.tf32.tf32.f32 "
        "{%0,%1,%2,%3}, {%4,%5,%6,%7}, {%8,%9}, {%0,%1,%2,%3};"
        : "+f"(c[0]), "+f"(c[1]), "+f"(c[2]), "+f"(c[3])
        : "r"(a0), "r"(a1), "r"(a2), "r"(a3), "r"(b0), "r"(b1));
}

// ============================================================================
// 1) scatter-mean accumulate
// ============================================================================
__global__ void scatter_kernel(const float* __restrict__ pts,
                               const float* __restrict__ feats, int n) {
    int i = blockIdx.x * blockDim.x + threadIdx.x;
    if (i >= n) return;
    float px = pts[3 * i + 0];
    float py = pts[3 * i + 1];
    float pz = pts[3 * i + 2];
    int bx = (int)floorf(px);
    int by = (int)floorf(py);
    int bz = (int)floorf(pz);
    bx = min(max(bx, 0), G - 1);
    by = min(max(by, 0), G - 1);
    bz = min(max(bz, 0), G - 1);
    int fl = (bx * G + by) * G + bz;

    atomicAdd(&g_cnt[fl], 1.0f);

    const float4* f4 = (const float4*)(feats + (size_t)i * INC);
    float4* dst = (float4*)(g_voxsum + (size_t)fl * INC);
#pragma unroll
    for (int k = 0; k < INC / 4; k++) {
        float4 v = f4[k];
        atomicAdd(dst + k, v);
    }
}

// ============================================================================
// 2) normalize sums -> means (in place)
// ============================================================================
__global__ void normalize_kernel() {
    int t = blockIdx.x * blockDim.x + threadIdx.x;
    if (t >= NVOX * (INC / 4)) return;
    int vox = t >> 3;
    float c = g_cnt[vox];
    float inv = 1.0f / fmaxf(c, 1.0f);
    float4* p = (float4*)g_voxsum + t;
    float4 v = *p;
    v.x *= inv; v.y *= inv; v.z *= inv; v.w *= inv;
    *p = v;
}

// ============================================================================
// 2b) W_conv -> B-fragment layout (tf32-rounded), one coalesced LDG.64 per frag.
//     Wc layout: [dx][dy][dz][ci][co] (tap = (dx*3+dy)*3+dz).
//     Frag (tap, ks, nt, lane): b0 = W[tap][ks*8 + lane%4    ][nt*8 + lane/4]
//                               b1 = W[tap][ks*8 + lane%4 + 4][nt*8 + lane/4]
// ============================================================================
__global__ void wfrag_kernel(const float* __restrict__ Wc) {
    int i = blockIdx.x * blockDim.x + threadIdx.x;   // (tap,ks,nt,lane)
    if (i >= 27 * 4 * 8 * 32) return;
    int lane = i & 31;
    int nt   = (i >> 5) & 7;
    int ks   = (i >> 8) & 3;
    int tap  = i >> 10;
    int ci = ks * 8 + (lane & 3);
    int co = nt * 8 + (lane >> 2);
    unsigned u0 = cvt_tf32(Wc[((size_t)tap * 32 + ci) * 64 + co]);
    unsigned u1 = cvt_tf32(Wc[((size_t)tap * 32 + ci + 4) * 64 + co]);
    g_wfrag[(size_t)i * 2 + 0] = __uint_as_float(u0);
    g_wfrag[(size_t)i * 2 + 1] = __uint_as_float(u1);
}

// ============================================================================
// 3) conv as implicit GEMM on tf32 mma.sync.
//    CTA = one (x,y) column: M=64 z, N=64 co, K = 27 taps x 32 ci.
//    8 warps = 4 m-tiles(16z) x 2 n-halves(32co). A from 3 smem panes
//    (x' fixed per dx iter), row stride 36 words -> conflict-free frag LDS.
//    B frags from g_wfrag (coalesced LDG.64). fp32 accumulation in frags.
// ============================================================================
__global__ __launch_bounds__(256) void conv_kernel() {
    __shared__ unsigned pane[3 * PANE_ROWS * PANE_STRIDE];   // 28512 B

    const int x = blockIdx.x, y = blockIdx.y;
    const int tid  = threadIdx.x;
    const int lane = tid & 31;
    const int warp = tid >> 5;
    const int mw   = warp & 3;       // m-tile: z0w = 16*mw
    const int nh   = warp >> 2;      // n-half: co base = 32*nh
    const int z0w  = mw * 16;
    const int colbase = (x * G + y) * G;

    float acc[4][4];                 // [nt][frag]
#pragma unroll
    for (int nt = 0; nt < 4; nt++)
#pragma unroll
        for (int j = 0; j < 4; j++) acc[nt][j] = 0.0f;

    const float2* wfp = (const float2*)g_wfrag;

#pragma unroll 1
    for (int dx = 0; dx < 3; dx++) {
        __syncthreads();
        int gx = x + dx - 1;
        // stage 3 y-panes for this gx: rows gz = -1..64 (zero padded), tf32-rounded
        for (int i = tid; i < 3 * PANE_ROWS * 8; i += 256) {
            int c4  = i & 7;
            int row = (i >> 3) % PANE_ROWS;
            int p   = (i >> 3) / PANE_ROWS;
            int gy = y + p - 1;
            int gz = row - 1;
            float4 v = make_float4(0.f, 0.f, 0.f, 0.f);
            if ((unsigned)gx < G && (unsigned)gy < G && (unsigned)gz < G)
                v = *(const float4*)(g_voxsum + (((size_t)(gx * G + gy) * G + gz) << 5) + c4 * 4);
            unsigned* dst = pane + (p * PANE_ROWS + row) * PANE_STRIDE + c4 * 4;
            dst[0] = cvt_tf32(v.x);
            dst[1] = cvt_tf32(v.y);
            dst[2] = cvt_tf32(v.z);
            dst[3] = cvt_tf32(v.w);
        }
        __syncthreads();

#pragma unroll 1
        for (int dy = 0; dy < 3; dy++) {
            const unsigned* pb = pane + dy * PANE_ROWS * PANE_STRIDE;
#pragma unroll 1
            for (int dz = 0; dz < 3; dz++) {
                int tap = (dx * 3 + dy) * 3 + dz;

                // B fragments for this tap: 16 coalesced LDG.64
                float2 bf[4][4];     // [ks][nt]
#pragma unroll
                for (int ks = 0; ks < 4; ks++)
#pragma unroll
                    for (int nt = 0; nt < 4; nt++)
                        bf[ks][nt] = wfp[((size_t)(tap * 4 + ks) * 8 + nh * 4 + nt) * 32 + lane];

#pragma unroll
                for (int ks = 0; ks < 4; ks++) {
                    int rowa = z0w + dz + (lane >> 2);
                    int cola = ks * 8 + (lane & 3);
                    const unsigned* ap = pb + rowa * PANE_STRIDE + cola;
                    unsigned a0 = ap[0];
                    unsigned a1 = ap[8 * PANE_STRIDE];
                    unsigned a2 = ap[4];
                    unsigned a3 = ap[8 * PANE_STRIDE + 4];
#pragma unroll
                    for (int nt = 0; nt < 4; nt++)
                        mma_tf32(acc[nt], a0, a1, a2, a3,
                                 __float_as_uint(bf[ks][nt].x),
                                 __float_as_uint(bf[ks][nt].y));
                }
            }
        }
    }

    // epilogue: occupancy mask + store
    int z1 = z0w + (lane >> 2);
    int z2 = z1 + 8;
    float occ1 = (g_cnt[colbase + z1] > 0.0f) ? 1.0f : 0.0f;
    float occ2 = (g_cnt[colbase + z2] > 0.0f) ? 1.0f : 0.0f;
#pragma unroll
    for (int nt = 0; nt < 4; nt++) {
        int co = nh * 32 + nt * 8 + (lane & 3) * 2;
        float2 v1 = make_float2(acc[nt][0] * occ1, acc[nt][1] * occ1);
        float2 v2 = make_float2(acc[nt][2] * occ2, acc[nt][3] * occ2);
        *(float2*)(g_conv + (size_t)(colbase + z1) * OUTC + co) = v1;
        *(float2*)(g_conv + (size_t)(colbase + z2) * OUTC + co) = v2;
    }
}

// ============================================================================
// 4a) residual linear (R5 measured-best: 48 regs, 56% occ, ~300us)
// ============================================================================
__global__ __launch_bounds__(256) void residual_kernel(const float* __restrict__ feats,
                                                       const float* __restrict__ Wlin,
                                                       const float* __restrict__ blin,
                                                       float* __restrict__ out, int n) {
    const int lane   = threadIdx.x & 31;
    const int gwarp  = (blockIdx.x * blockDim.x + threadIdx.x) >> 5;
    const int nwarps = (gridDim.x * blockDim.x) >> 5;
    const int h      = gwarp & 1;
    const int co     = h * 32 + lane;

    float wreg[INC];
    {
        const float4* r0 = (const float4*)(Wlin + (size_t)co * INC);
#pragma unroll
        for (int k = 0; k < INC / 4; k++) {
            float4 a = r0[k];
            wreg[4 * k + 0] = a.x;
            wreg[4 * k + 1] = a.y;
            wreg[4 * k + 2] = a.z;
            wreg[4 * k + 3] = a.w;
        }
    }
    const float bl = blin[co];

    for (int pair = gwarp; pair < 2 * n; pair += nwarps) {
        int p = pair >> 1;
        float fv = feats[(size_t)p * INC + lane];
        float acc = bl;
#pragma unroll
        for (int ci = 0; ci < INC; ci++) {
            float f = __shfl_sync(0xffffffffu, fv, ci);
            acc += f * wreg[ci];
        }
        out[(size_t)p * OUTC + co] = acc;
    }
}

// ============================================================================
// 4b) trilinear devoxelize: gathers accumulate onto residual already in out
// ============================================================================
__global__ __launch_bounds__(256) void devox_kernel(const float* __restrict__ pts,
                                                    float* __restrict__ out, int n) {
    const int lane   = threadIdx.x & 31;
    const int warp   = (blockIdx.x * blockDim.x + threadIdx.x) >> 5;
    const int nwarps = (gridDim.x * blockDim.x) >> 5;

    for (int p = warp; p < n; p += nwarps) {
        float px = pts[3 * p + 0];
        float py = pts[3 * p + 1];
        float pz = pts[3 * p + 2];
        int bx = (int)floorf(px);
        int by = (int)floorf(py);
        int bz = (int)floorf(pz);
        float fx = px - (float)bx;
        float fy = py - (float)by;
        float fz = pz - (float)bz;

        float2* orow = (float2*)out + (size_t)p * (OUTC / 2);
        float2 acc = orow[lane];

#pragma unroll
        for (int c = 0; c < 8; c++) {
            int dx = (c >> 2) & 1, dy = (c >> 1) & 1, dz = c & 1;
            int nx = bx + dx, ny = by + dy, nz = bz + dz;
            float w = (dx ? fx : 1.0f - fx) * (dy ? fy : 1.0f - fy) * (dz ? fz : 1.0f - fz);
            if ((unsigned)nx < G && (unsigned)ny < G && (unsigned)nz < G) {
                int fl = (nx * G + ny) * G + nz;
                const float2* row = (const float2*)(g_conv + (size_t)fl * OUTC);
                float2 v = row[lane];
                acc.x += w * v.x;
                acc.y += w * v.y;
            }
        }

        orow[lane] = acc;
    }
}

// ============================================================================
extern "C" void kernel_launch(void* const* d_in, const int* in_sizes, int n_in,
                              void* d_out, int out_size) {
    const float* pts   = (const float*)d_in[0];
    const float* feats = (const float*)d_in[1];
    const float* Wc    = (const float*)d_in[2];
    const float* Wl    = (const float*)d_in[3];
    const float* bl    = (const float*)d_in[4];
    float* out = (float*)d_out;
    int npts = in_sizes[0] / 3;

    void *p_sum = nullptr, *p_cnt = nullptr;
    cudaGetSymbolAddress(&p_sum, g_voxsum);
    cudaGetSymbolAddress(&p_cnt, g_cnt);
    cudaMemsetAsync(p_sum, 0, (size_t)NVOX * INC * sizeof(float));
    cudaMemsetAsync(p_cnt, 0, (size_t)NVOX * sizeof(float));

    scatter_kernel<<<(npts + 255) / 256, 256>>>(pts, feats, npts);

    normalize_kernel<<<(NVOX * (INC / 4) + 255) / 256, 256>>>();

    wfrag_kernel<<<(27 * 4 * 8 * 32 + 255) / 256, 256>>>(Wc);

    dim3 cgrid(G, G);
    conv_kernel<<<cgrid, 256>>>();

    residual_kernel<<<2048, 256>>>(feats, Wl, bl, out, npts);

    devox_kernel<<<4096, 256>>>(pts, out, npts);
}

// round 9
// speedup vs baseline: 2.3863x; 1.3934x over previous
#include <cuda_runtime.h>
#include <cuda_bf16.h>
#include <cstdint>

#define G     64
#define NVOX  (G*G*G)
#define INC   32
#define OUTC  64
#define PANE_ROWS   66
#define PANE_STRIDE 36   // words; 36 mod 32 = 4 -> frag LDS bank-conflict-free

// ---- device scratch (allocation-free rule: static __device__ arrays) ----
__device__ float g_voxsum[NVOX * INC];        // 32 MB: scatter sums -> means
__device__ float g_cnt[NVOX];                 //  1 MB: per-voxel point counts
__device__ float g_conv[NVOX * OUTC];         // 64 MB: conv output (occ-masked)
__device__ float g_wfrag[27 * 4 * 8 * 32 * 2]; // W_conv in mma B-fragment order (tf32)

__device__ __forceinline__ unsigned cvt_tf32(float f) {
    unsigned u;
    asm("cvt.rna.tf32.f32 %0, %1;" : "=r"(u) : "f"(f));
    return u;
}

__device__ __forceinline__ void mma_tf32(float c[4], unsigned a0, unsigned a1,
                                         unsigned a2, unsigned a3,
                                         unsigned b0, unsigned b1) {
    asm volatile(
        "mma.sync.aligned.m16n8k8.row.col.f32.tf32.tf32.f32 "
        "{%0,%1,%2,%3}, {%4,%5,%6,%7}, {%8,%9}, {%0,%1,%2,%3};"
        : "+f"(c[0]), "+f"(c[1]), "+f"(c[2]), "+f"(c[3])
        : "r"(a0), "r"(a1), "r"(a2), "r"(a3), "r"(b0), "r"(b1));
}

// ============================================================================
// 1) scatter-mean accumulate
// ============================================================================
__global__ void scatter_kernel(const float* __restrict__ pts,
                               const float* __restrict__ feats, int n) {
    int i = blockIdx.x * blockDim.x + threadIdx.x;
    if (i >= n) return;
    float px = pts[3 * i + 0];
    float py = pts[3 * i + 1];
    float pz = pts[3 * i + 2];
    int bx = (int)floorf(px);
    int by = (int)floorf(py);
    int bz = (int)floorf(pz);
    bx = min(max(bx, 0), G - 1);
    by = min(max(by, 0), G - 1);
    bz = min(max(bz, 0), G - 1);
    int fl = (bx * G + by) * G + bz;

    atomicAdd(&g_cnt[fl], 1.0f);

    const float4* f4 = (const float4*)(feats + (size_t)i * INC);
    float4* dst = (float4*)(g_voxsum + (size_t)fl * INC);
#pragma unroll
    for (int k = 0; k < INC / 4; k++) {
        float4 v = f4[k];
        atomicAdd(dst + k, v);
    }
}

// ============================================================================
// 2) normalize sums -> means (in place)
// ============================================================================
__global__ void normalize_kernel() {
    int t = blockIdx.x * blockDim.x + threadIdx.x;
    if (t >= NVOX * (INC / 4)) return;
    int vox = t >> 3;
    float c = g_cnt[vox];
    float inv = 1.0f / fmaxf(c, 1.0f);
    float4* p = (float4*)g_voxsum + t;
    float4 v = *p;
    v.x *= inv; v.y *= inv; v.z *= inv; v.w *= inv;
    *p = v;
}

// ============================================================================
// 2b) W_conv -> B-fragment layout (tf32-rounded)
// ============================================================================
__global__ void wfrag_kernel(const float* __restrict__ Wc) {
    int i = blockIdx.x * blockDim.x + threadIdx.x;   // (tap,ks,nt,lane)
    if (i >= 27 * 4 * 8 * 32) return;
    int lane = i & 31;
    int nt   = (i >> 5) & 7;
    int ks   = (i >> 8) & 3;
    int tap  = i >> 10;
    int ci = ks * 8 + (lane & 3);
    int co = nt * 8 + (lane >> 2);
    unsigned u0 = cvt_tf32(Wc[((size_t)tap * 32 + ci) * 64 + co]);
    unsigned u1 = cvt_tf32(Wc[((size_t)tap * 32 + ci + 4) * 64 + co]);
    g_wfrag[(size_t)i * 2 + 0] = __uint_as_float(u0);
    g_wfrag[(size_t)i * 2 + 1] = __uint_as_float(u1);
}

// ============================================================================
// 3) conv as implicit GEMM on tf32 mma.sync (R8 measured: 259us, tensor=38%)
// ============================================================================
__global__ __launch_bounds__(256) void conv_kernel() {
    __shared__ unsigned pane[3 * PANE_ROWS * PANE_STRIDE];   // 28512 B

    const int x = blockIdx.x, y = blockIdx.y;
    const int tid  = threadIdx.x;
    const int lane = tid & 31;
    const int warp = tid >> 5;
    const int mw   = warp & 3;       // m-tile: z0w = 16*mw
    const int nh   = warp >> 2;      // n-half: co base = 32*nh
    const int z0w  = mw * 16;
    const int colbase = (x * G + y) * G;

    float acc[4][4];                 // [nt][frag]
#pragma unroll
    for (int nt = 0; nt < 4; nt++)
#pragma unroll
        for (int j = 0; j < 4; j++) acc[nt][j] = 0.0f;

    const float2* wfp = (const float2*)g_wfrag;

#pragma unroll 1
    for (int dx = 0; dx < 3; dx++) {
        __syncthreads();
        int gx = x + dx - 1;
        for (int i = tid; i < 3 * PANE_ROWS * 8; i += 256) {
            int c4  = i & 7;
            int row = (i >> 3) % PANE_ROWS;
            int p   = (i >> 3) / PANE_ROWS;
            int gy = y + p - 1;
            int gz = row - 1;
            float4 v = make_float4(0.f, 0.f, 0.f, 0.f);
            if ((unsigned)gx < G && (unsigned)gy < G && (unsigned)gz < G)
                v = *(const float4*)(g_voxsum + (((size_t)(gx * G + gy) * G + gz) << 5) + c4 * 4);
            unsigned* dst = pane + (p * PANE_ROWS + row) * PANE_STRIDE + c4 * 4;
            dst[0] = cvt_tf32(v.x);
            dst[1] = cvt_tf32(v.y);
            dst[2] = cvt_tf32(v.z);
            dst[3] = cvt_tf32(v.w);
        }
        __syncthreads();

#pragma unroll 1
        for (int dy = 0; dy < 3; dy++) {
            const unsigned* pb = pane + dy * PANE_ROWS * PANE_STRIDE;
#pragma unroll 1
            for (int dz = 0; dz < 3; dz++) {
                int tap = (dx * 3 + dy) * 3 + dz;

                float2 bf[4][4];     // [ks][nt]
#pragma unroll
                for (int ks = 0; ks < 4; ks++)
#pragma unroll
                    for (int nt = 0; nt < 4; nt++)
                        bf[ks][nt] = wfp[((size_t)(tap * 4 + ks) * 8 + nh * 4 + nt) * 32 + lane];

#pragma unroll
                for (int ks = 0; ks < 4; ks++) {
                    int rowa = z0w + dz + (lane >> 2);
                    int cola = ks * 8 + (lane & 3);
                    const unsigned* ap = pb + rowa * PANE_STRIDE + cola;
                    unsigned a0 = ap[0];
                    unsigned a1 = ap[8 * PANE_STRIDE];
                    unsigned a2 = ap[4];
                    unsigned a3 = ap[8 * PANE_STRIDE + 4];
#pragma unroll
                    for (int nt = 0; nt < 4; nt++)
                        mma_tf32(acc[nt], a0, a1, a2, a3,
                                 __float_as_uint(bf[ks][nt].x),
                                 __float_as_uint(bf[ks][nt].y));
                }
            }
        }
    }

    int z1 = z0w + (lane >> 2);
    int z2 = z1 + 8;
    float occ1 = (g_cnt[colbase + z1] > 0.0f) ? 1.0f : 0.0f;
    float occ2 = (g_cnt[colbase + z2] > 0.0f) ? 1.0f : 0.0f;
#pragma unroll
    for (int nt = 0; nt < 4; nt++) {
        int co = nh * 32 + nt * 8 + (lane & 3) * 2;
        float2 v1 = make_float2(acc[nt][0] * occ1, acc[nt][1] * occ1);
        float2 v2 = make_float2(acc[nt][2] * occ2, acc[nt][3] * occ2);
        *(float2*)(g_conv + (size_t)(colbase + z1) * OUTC + co) = v1;
        *(float2*)(g_conv + (size_t)(colbase + z2) * OUTC + co) = v2;
    }
}

// ============================================================================
// 4a) residual linear as tf32 MMA: out = b + feats @ W_lin^T.
//     Warp tile = 16 points x 64 co, K=32 (4 k-steps x 8 n-tiles).
//     B frags + bias staged once per CTA in smem; A frags via scalar LDG
//     (each quad fully consumes its point's 128B feats line).
// ============================================================================
__global__ __launch_bounds__(256) void residual_kernel(const float* __restrict__ feats,
                                                       const float* __restrict__ Wlin,
                                                       const float* __restrict__ blin,
                                                       float* __restrict__ out, int n) {
    __shared__ uint2 bsm[8 * 4 * 32];   // [nt][ks][lane]  8KB
    __shared__ float2 bbias[8 * 4];     // [nt][tig]

    const int tid  = threadIdx.x;
    const int lane = tid & 31;
    const int warp = tid >> 5;

    // build W_lin B-fragments (tf32) once per CTA
    for (int i = tid; i < 8 * 4 * 32; i += 256) {
        int l  = i & 31;
        int ks = (i >> 5) & 3;
        int nt = i >> 7;
        int k = ks * 8 + (l & 3);
        int nn = nt * 8 + (l >> 2);
        uint2 b;
        b.x = cvt_tf32(Wlin[(size_t)nn * INC + k]);
        b.y = cvt_tf32(Wlin[(size_t)nn * INC + k + 4]);
        bsm[i] = b;
    }
    if (tid < 32) {
        int nt = tid >> 2, tig = tid & 3;
        bbias[nt * 4 + tig] = make_float2(blin[nt * 8 + 2 * tig], blin[nt * 8 + 2 * tig + 1]);
    }
    __syncthreads();

    const int gwarp  = blockIdx.x * 8 + warp;
    const int nwarps = gridDim.x * 8;
    const int ntiles = (n + 15) >> 4;
    const int gid = lane >> 2;         // 0..7
    const int tig = lane & 3;          // 0..3

    for (int tile = gwarp; tile < ntiles; tile += nwarps) {
        int p0 = tile * 16;
        int pr1 = p0 + gid;
        int pr2 = p0 + gid + 8;
        bool v1 = pr1 < n, v2 = pr2 < n;
        const float* f1 = feats + (size_t)pr1 * INC;
        const float* f2 = feats + (size_t)pr2 * INC;

        float acc[8][4];
#pragma unroll
        for (int nt = 0; nt < 8; nt++) {
            float2 bb = bbias[nt * 4 + tig];
            acc[nt][0] = bb.x; acc[nt][1] = bb.y;
            acc[nt][2] = bb.x; acc[nt][3] = bb.y;
        }

#pragma unroll
        for (int ks = 0; ks < 4; ks++) {
            int c = ks * 8 + tig;
            unsigned a0 = v1 ? cvt_tf32(f1[c])     : 0u;
            unsigned a1 = v2 ? cvt_tf32(f2[c])     : 0u;
            unsigned a2 = v1 ? cvt_tf32(f1[c + 4]) : 0u;
            unsigned a3 = v2 ? cvt_tf32(f2[c + 4]) : 0u;
#pragma unroll
            for (int nt = 0; nt < 8; nt++) {
                uint2 b = bsm[(nt * 4 + ks) * 32 + lane];
                mma_tf32(acc[nt], a0, a1, a2, a3, b.x, b.y);
            }
        }

        if (v1) {
            float2* o1 = (float2*)(out + (size_t)pr1 * OUTC);
#pragma unroll
            for (int nt = 0; nt < 8; nt++)
                o1[nt * 4 + tig] = make_float2(acc[nt][0], acc[nt][1]);
        }
        if (v2) {
            float2* o2 = (float2*)(out + (size_t)pr2 * OUTC);
#pragma unroll
            for (int nt = 0; nt < 8; nt++)
                o2[nt * 4 + tig] = make_float2(acc[nt][2], acc[nt][3]);
        }
    }
}

// ============================================================================
// 4b) trilinear devoxelize: gathers accumulate onto residual already in out
// ============================================================================
__global__ __launch_bounds__(256) void devox_kernel(const float* __restrict__ pts,
                                                    float* __restrict__ out, int n) {
    const int lane   = threadIdx.x & 31;
    const int warp   = (blockIdx.x * blockDim.x + threadIdx.x) >> 5;
    const int nwarps = (gridDim.x * blockDim.x) >> 5;

    for (int p = warp; p < n; p += nwarps) {
        float px = pts[3 * p + 0];
        float py = pts[3 * p + 1];
        float pz = pts[3 * p + 2];
        int bx = (int)floorf(px);
        int by = (int)floorf(py);
        int bz = (int)floorf(pz);
        float fx = px - (float)bx;
        float fy = py - (float)by;
        float fz = pz - (float)bz;

        float2* orow = (float2*)out + (size_t)p * (OUTC / 2);
        float2 acc = orow[lane];

#pragma unroll
        for (int c = 0; c < 8; c++) {
            int dx = (c >> 2) & 1, dy = (c >> 1) & 1, dz = c & 1;
            int nx = bx + dx, ny = by + dy, nz = bz + dz;
            float w = (dx ? fx : 1.0f - fx) * (dy ? fy : 1.0f - fy) * (dz ? fz : 1.0f - fz);
            if ((unsigned)nx < G && (unsigned)ny < G && (unsigned)nz < G) {
                int fl = (nx * G + ny) * G + nz;
                const float2* row = (const float2*)(g_conv + (size_t)fl * OUTC);
                float2 v = row[lane];
                acc.x += w * v.x;
                acc.y += w * v.y;
            }
        }

        orow[lane] = acc;
    }
}

// ============================================================================
extern "C" void kernel_launch(void* const* d_in, const int* in_sizes, int n_in,
                              void* d_out, int out_size) {
    const float* pts   = (const float*)d_in[0];
    const float* feats = (const float*)d_in[1];
    const float* Wc    = (const float*)d_in[2];
    const float* Wl    = (const float*)d_in[3];
    const float* bl    = (const float*)d_in[4];
    float* out = (float*)d_out;
    int npts = in_sizes[0] / 3;

    void *p_sum = nullptr, *p_cnt = nullptr;
    cudaGetSymbolAddress(&p_sum, g_voxsum);
    cudaGetSymbolAddress(&p_cnt, g_cnt);
    cudaMemsetAsync(p_sum, 0, (size_t)NVOX * INC * sizeof(float));
    cudaMemsetAsync(p_cnt, 0, (size_t)NVOX * sizeof(float));

    scatter_kernel<<<(npts + 255) / 256, 256>>>(pts, feats, npts);

    normalize_kernel<<<(NVOX * (INC / 4) + 255) / 256, 256>>>();

    wfrag_kernel<<<(27 * 4 * 8 * 32 + 255) / 256, 256>>>(Wc);

    dim3 cgrid(G, G);
    conv_kernel<<<cgrid, 256>>>();

    residual_kernel<<<2048, 256>>>(feats, Wl, bl, out, npts);

    devox_kernel<<<4096, 256>>>(pts, out, npts);
}

// round 10
// speedup vs baseline: 2.4126x; 1.0110x over previous
#include <cuda_runtime.h>
#include <cuda_fp16.h>
#include <cstdint>

#define G     64
#define NVOX  (G*G*G)
#define INC   32
#define OUTC  64
#define PANE_ROWS   66
#define PANE_STRIDE 36   // words; 36 mod 32 = 4 -> frag LDS bank-conflict-free

// ---- device scratch (allocation-free rule: static __device__ arrays) ----
__device__ float  g_voxsum[NVOX * INC];        // 32 MB: scatter sums (raw)
__device__ float  g_cnt[NVOX];                 //  1 MB: per-voxel point counts
__device__ __half g_conv[NVOX * OUTC];         // 32 MB: conv output (occ-masked, fp16)
__device__ float  g_wfrag[27 * 4 * 8 * 32 * 2]; // W_conv in mma B-fragment order (tf32)

__device__ __forceinline__ unsigned cvt_tf32(float f) {
    unsigned u;
    asm("cvt.rna.tf32.f32 %0, %1;" : "=r"(u) : "f"(f));
    return u;
}

__device__ __forceinline__ void mma_tf32(float c[4], unsigned a0, unsigned a1,
                                         unsigned a2, unsigned a3,
                                         unsigned b0, unsigned b1) {
    asm volatile(
        "mma.sync.aligned.m16n8k8.row.col.f32.tf32.tf32.f32 "
        "{%0,%1,%2,%3}, {%4,%5,%6,%7}, {%8,%9}, {%0,%1,%2,%3};"
        : "+f"(c[0]), "+f"(c[1]), "+f"(c[2]), "+f"(c[3])
        : "r"(a0), "r"(a1), "r"(a2), "r"(a3), "r"(b0), "r"(b1));
}

// ============================================================================
// 1) scatter-mean accumulate
// ============================================================================
__global__ void scatter_kernel(const float* __restrict__ pts,
                               const float* __restrict__ feats, int n) {
    int i = blockIdx.x * blockDim.x + threadIdx.x;
    if (i >= n) return;
    float px = pts[3 * i + 0];
    float py = pts[3 * i + 1];
    float pz = pts[3 * i + 2];
    int bx = (int)floorf(px);
    int by = (int)floorf(py);
    int bz = (int)floorf(pz);
    bx = min(max(bx, 0), G - 1);
    by = min(max(by, 0), G - 1);
    bz = min(max(bz, 0), G - 1);
    int fl = (bx * G + by) * G + bz;

    atomicAdd(&g_cnt[fl], 1.0f);

    const float4* f4 = (const float4*)(feats + (size_t)i * INC);
    float4* dst = (float4*)(g_voxsum + (size_t)fl * INC);
#pragma unroll
    for (int k = 0; k < INC / 4; k++) {
        float4 v = f4[k];
        atomicAdd(dst + k, v);
    }
}

// ============================================================================
// 2) W_conv -> B-fragment layout (tf32-rounded)
// ============================================================================
__global__ void wfrag_kernel(const float* __restrict__ Wc) {
    int i = blockIdx.x * blockDim.x + threadIdx.x;   // (tap,ks,nt,lane)
    if (i >= 27 * 4 * 8 * 32) return;
    int lane = i & 31;
    int nt   = (i >> 5) & 7;
    int ks   = (i >> 8) & 3;
    int tap  = i >> 10;
    int ci = ks * 8 + (lane & 3);
    int co = nt * 8 + (lane >> 2);
    unsigned u0 = cvt_tf32(Wc[((size_t)tap * 32 + ci) * 64 + co]);
    unsigned u1 = cvt_tf32(Wc[((size_t)tap * 32 + ci + 4) * 64 + co]);
    g_wfrag[(size_t)i * 2 + 0] = __uint_as_float(u0);
    g_wfrag[(size_t)i * 2 + 1] = __uint_as_float(u1);
}

// ============================================================================
// 3) conv as implicit GEMM on tf32 mma.sync.
//    Normalize (1/max(cnt,1)) is folded into pane staging, so g_voxsum stays
//    raw sums and the standalone normalize pass is gone. Output stored fp16.
// ============================================================================
__global__ __launch_bounds__(256) void conv_kernel() {
    __shared__ unsigned pane[3 * PANE_ROWS * PANE_STRIDE];   // 28512 B

    const int x = blockIdx.x, y = blockIdx.y;
    const int tid  = threadIdx.x;
    const int lane = tid & 31;
    const int warp = tid >> 5;
    const int mw   = warp & 3;       // m-tile: z0w = 16*mw
    const int nh   = warp >> 2;      // n-half: co base = 32*nh
    const int z0w  = mw * 16;
    const int colbase = (x * G + y) * G;

    float acc[4][4];                 // [nt][frag]
#pragma unroll
    for (int nt = 0; nt < 4; nt++)
#pragma unroll
        for (int j = 0; j < 4; j++) acc[nt][j] = 0.0f;

    const float2* wfp = (const float2*)g_wfrag;

#pragma unroll 1
    for (int dx = 0; dx < 3; dx++) {
        __syncthreads();
        int gx = x + dx - 1;
        for (int i = tid; i < 3 * PANE_ROWS * 8; i += 256) {
            int c4  = i & 7;
            int row = (i >> 3) % PANE_ROWS;
            int p   = (i >> 3) / PANE_ROWS;
            int gy = y + p - 1;
            int gz = row - 1;
            float4 v = make_float4(0.f, 0.f, 0.f, 0.f);
            if ((unsigned)gx < G && (unsigned)gy < G && (unsigned)gz < G) {
                int vox = (gx * G + gy) * G + gz;
                v = *(const float4*)(g_voxsum + ((size_t)vox << 5) + c4 * 4);
                float inv = 1.0f / fmaxf(g_cnt[vox], 1.0f);   // fold normalize
                v.x *= inv; v.y *= inv; v.z *= inv; v.w *= inv;
            }
            unsigned* dst = pane + (p * PANE_ROWS + row) * PANE_STRIDE + c4 * 4;
            dst[0] = cvt_tf32(v.x);
            dst[1] = cvt_tf32(v.y);
            dst[2] = cvt_tf32(v.z);
            dst[3] = cvt_tf32(v.w);
        }
        __syncthreads();

#pragma unroll 1
        for (int dy = 0; dy < 3; dy++) {
            const unsigned* pb = pane + dy * PANE_ROWS * PANE_STRIDE;
#pragma unroll 1
            for (int dz = 0; dz < 3; dz++) {
                int tap = (dx * 3 + dy) * 3 + dz;

                float2 bf[4][4];     // [ks][nt]
#pragma unroll
                for (int ks = 0; ks < 4; ks++)
#pragma unroll
                    for (int nt = 0; nt < 4; nt++)
                        bf[ks][nt] = wfp[((size_t)(tap * 4 + ks) * 8 + nh * 4 + nt) * 32 + lane];

#pragma unroll
                for (int ks = 0; ks < 4; ks++) {
                    int rowa = z0w + dz + (lane >> 2);
                    int cola = ks * 8 + (lane & 3);
                    const unsigned* ap = pb + rowa * PANE_STRIDE + cola;
                    unsigned a0 = ap[0];
                    unsigned a1 = ap[8 * PANE_STRIDE];
                    unsigned a2 = ap[4];
                    unsigned a3 = ap[8 * PANE_STRIDE + 4];
#pragma unroll
                    for (int nt = 0; nt < 4; nt++)
                        mma_tf32(acc[nt], a0, a1, a2, a3,
                                 __float_as_uint(bf[ks][nt].x),
                                 __float_as_uint(bf[ks][nt].y));
                }
            }
        }
    }

    int z1 = z0w + (lane >> 2);
    int z2 = z1 + 8;
    float occ1 = (g_cnt[colbase + z1] > 0.0f) ? 1.0f : 0.0f;
    float occ2 = (g_cnt[colbase + z2] > 0.0f) ? 1.0f : 0.0f;
#pragma unroll
    for (int nt = 0; nt < 4; nt++) {
        int co = nh * 32 + nt * 8 + (lane & 3) * 2;
        __half2 v1 = __floats2half2_rn(acc[nt][0] * occ1, acc[nt][1] * occ1);
        __half2 v2 = __floats2half2_rn(acc[nt][2] * occ2, acc[nt][3] * occ2);
        *(__half2*)(g_conv + (size_t)(colbase + z1) * OUTC + co) = v1;
        *(__half2*)(g_conv + (size_t)(colbase + z2) * OUTC + co) = v2;
    }
}

// ============================================================================
// 4a) residual linear as tf32 MMA (R9 measured-good)
// ============================================================================
__global__ __launch_bounds__(256) void residual_kernel(const float* __restrict__ feats,
                                                       const float* __restrict__ Wlin,
                                                       const float* __restrict__ blin,
                                                       float* __restrict__ out, int n) {
    __shared__ uint2 bsm[8 * 4 * 32];   // [nt][ks][lane]  8KB
    __shared__ float2 bbias[8 * 4];     // [nt][tig]

    const int tid  = threadIdx.x;
    const int lane = tid & 31;
    const int warp = tid >> 5;

    for (int i = tid; i < 8 * 4 * 32; i += 256) {
        int l  = i & 31;
        int ks = (i >> 5) & 3;
        int nt = i >> 7;
        int k = ks * 8 + (l & 3);
        int nn = nt * 8 + (l >> 2);
        uint2 b;
        b.x = cvt_tf32(Wlin[(size_t)nn * INC + k]);
        b.y = cvt_tf32(Wlin[(size_t)nn * INC + k + 4]);
        bsm[i] = b;
    }
    if (tid < 32) {
        int nt = tid >> 2, tig = tid & 3;
        bbias[nt * 4 + tig] = make_float2(blin[nt * 8 + 2 * tig], blin[nt * 8 + 2 * tig + 1]);
    }
    __syncthreads();

    const int gwarp  = blockIdx.x * 8 + warp;
    const int nwarps = gridDim.x * 8;
    const int ntiles = (n + 15) >> 4;
    const int gid = lane >> 2;         // 0..7
    const int tig = lane & 3;          // 0..3

    for (int tile = gwarp; tile < ntiles; tile += nwarps) {
        int p0 = tile * 16;
        int pr1 = p0 + gid;
        int pr2 = p0 + gid + 8;
        bool v1 = pr1 < n, v2 = pr2 < n;
        const float* f1 = feats + (size_t)pr1 * INC;
        const float* f2 = feats + (size_t)pr2 * INC;

        float acc[8][4];
#pragma unroll
        for (int nt = 0; nt < 8; nt++) {
            float2 bb = bbias[nt * 4 + tig];
            acc[nt][0] = bb.x; acc[nt][1] = bb.y;
            acc[nt][2] = bb.x; acc[nt][3] = bb.y;
        }

#pragma unroll
        for (int ks = 0; ks < 4; ks++) {
            int c = ks * 8 + tig;
            unsigned a0 = v1 ? cvt_tf32(f1[c])     : 0u;
            unsigned a1 = v2 ? cvt_tf32(f2[c])     : 0u;
            unsigned a2 = v1 ? cvt_tf32(f1[c + 4]) : 0u;
            unsigned a3 = v2 ? cvt_tf32(f2[c + 4]) : 0u;
#pragma unroll
            for (int nt = 0; nt < 8; nt++) {
                uint2 b = bsm[(nt * 4 + ks) * 32 + lane];
                mma_tf32(acc[nt], a0, a1, a2, a3, b.x, b.y);
            }
        }

        if (v1) {
            float2* o1 = (float2*)(out + (size_t)pr1 * OUTC);
#pragma unroll
            for (int nt = 0; nt < 8; nt++)
                o1[nt * 4 + tig] = make_float2(acc[nt][0], acc[nt][1]);
        }
        if (v2) {
            float2* o2 = (float2*)(out + (size_t)pr2 * OUTC);
#pragma unroll
            for (int nt = 0; nt < 8; nt++)
                o2[nt * 4 + tig] = make_float2(acc[nt][2], acc[nt][3]);
        }
    }
}

// ============================================================================
// 4b) trilinear devoxelize: fp16 gathers (half traffic) onto residual in out
// ============================================================================
__global__ __launch_bounds__(256) void devox_kernel(const float* __restrict__ pts,
                                                    float* __restrict__ out, int n) {
    const int lane   = threadIdx.x & 31;
    const int warp   = (blockIdx.x * blockDim.x + threadIdx.x) >> 5;
    const int nwarps = (gridDim.x * blockDim.x) >> 5;

    for (int p = warp; p < n; p += nwarps) {
        float px = pts[3 * p + 0];
        float py = pts[3 * p + 1];
        float pz = pts[3 * p + 2];
        int bx = (int)floorf(px);
        int by = (int)floorf(py);
        int bz = (int)floorf(pz);
        float fx = px - (float)bx;
        float fy = py - (float)by;
        float fz = pz - (float)bz;

        float2* orow = (float2*)out + (size_t)p * (OUTC / 2);
        float2 acc = orow[lane];

#pragma unroll
        for (int c = 0; c < 8; c++) {
            int dx = (c >> 2) & 1, dy = (c >> 1) & 1, dz = c & 1;
            int nx = bx + dx, ny = by + dy, nz = bz + dz;
            float w = (dx ? fx : 1.0f - fx) * (dy ? fy : 1.0f - fy) * (dz ? fz : 1.0f - fz);
            if ((unsigned)nx < G && (unsigned)ny < G && (unsigned)nz < G) {
                int fl = (nx * G + ny) * G + nz;
                const __half2* row = (const __half2*)(g_conv + (size_t)fl * OUTC);
                float2 v = __half22float2(row[lane]);   // 64B/warp per corner
                acc.x += w * v.x;
                acc.y += w * v.y;
            }
        }

        orow[lane] = acc;
    }
}

// ============================================================================
extern "C" void kernel_launch(void* const* d_in, const int* in_sizes, int n_in,
                              void* d_out, int out_size) {
    const float* pts   = (const float*)d_in[0];
    const float* feats = (const float*)d_in[1];
    const float* Wc    = (const float*)d_in[2];
    const float* Wl    = (const float*)d_in[3];
    const float* bl    = (const float*)d_in[4];
    float* out = (float*)d_out;
    int npts = in_sizes[0] / 3;

    void *p_sum = nullptr, *p_cnt = nullptr;
    cudaGetSymbolAddress(&p_sum, g_voxsum);
    cudaGetSymbolAddress(&p_cnt, g_cnt);
    cudaMemsetAsync(p_sum, 0, (size_t)NVOX * INC * sizeof(float));
    cudaMemsetAsync(p_cnt, 0, (size_t)NVOX * sizeof(float));

    scatter_kernel<<<(npts + 255) / 256, 256>>>(pts, feats, npts);

    wfrag_kernel<<<(27 * 4 * 8 * 32 + 255) / 256, 256>>>(Wc);

    dim3 cgrid(G, G);
    conv_kernel<<<cgrid, 256>>>();

    residual_kernel<<<2048, 256>>>(feats, Wl, bl, out, npts);

    devox_kernel<<<4096, 256>>>(pts, out, npts);
}

// round 11
// speedup vs baseline: 2.4404x; 1.0115x over previous
#include <cuda_runtime.h>
#include <cuda_fp16.h>
#include <cstdint>

#define G     64
#define NVOX  (G*G*G)
#define INC   32
#define OUTC  64
#define PANE_ROWS   66
#define PANE_STRIDE 36   // words; 36 mod 32 = 4 -> frag LDS bank-conflict-free

// ---- device scratch (allocation-free rule: static __device__ arrays) ----
__device__ float  g_voxsum[NVOX * INC];        // 32 MB: scatter sums (raw)
__device__ float  g_cnt[NVOX];                 //  1 MB: per-voxel point counts
__device__ float  g_invcnt[NVOX];              //  1 MB: cnt>0 ? 1/cnt : 0
__device__ __half g_conv[NVOX * OUTC];         // 32 MB: conv output (occ-masked, fp16)
__device__ float  g_wfrag[27 * 4 * 8 * 32 * 2]; // W_conv in mma B-fragment order (tf32)

__device__ __forceinline__ unsigned cvt_tf32(float f) {
    unsigned u;
    asm("cvt.rna.tf32.f32 %0, %1;" : "=r"(u) : "f"(f));
    return u;
}

__device__ __forceinline__ void mma_tf32(float c[4], unsigned a0, unsigned a1,
                                         unsigned a2, unsigned a3,
                                         unsigned b0, unsigned b1) {
    asm volatile(
        "mma.sync.aligned.m16n8k8.row.col.f32.tf32.tf32.f32 "
        "{%0,%1,%2,%3}, {%4,%5,%6,%7}, {%8,%9}, {%0,%1,%2,%3};"
        : "+f"(c[0]), "+f"(c[1]), "+f"(c[2]), "+f"(c[3])
        : "r"(a0), "r"(a1), "r"(a2), "r"(a3), "r"(b0), "r"(b1));
}

// ============================================================================
// 1) scatter-mean accumulate
// ============================================================================
__global__ void scatter_kernel(const float* __restrict__ pts,
                               const float* __restrict__ feats, int n) {
    int i = blockIdx.x * blockDim.x + threadIdx.x;
    if (i >= n) return;
    float px = pts[3 * i + 0];
    float py = pts[3 * i + 1];
    float pz = pts[3 * i + 2];
    int bx = (int)floorf(px);
    int by = (int)floorf(py);
    int bz = (int)floorf(pz);
    bx = min(max(bx, 0), G - 1);
    by = min(max(by, 0), G - 1);
    bz = min(max(bz, 0), G - 1);
    int fl = (bx * G + by) * G + bz;

    atomicAdd(&g_cnt[fl], 1.0f);

    const float4* f4 = (const float4*)(feats + (size_t)i * INC);
    float4* dst = (float4*)(g_voxsum + (size_t)fl * INC);
#pragma unroll
    for (int k = 0; k < INC / 4; k++) {
        float4 v = f4[k];
        atomicAdd(dst + k, v);
    }
}

// ============================================================================
// 1b) per-voxel inverse counts: one MUFU per voxel instead of 19.5M in conv
// ============================================================================
__global__ void invcnt_kernel() {
    int v = blockIdx.x * blockDim.x + threadIdx.x;
    if (v >= NVOX) return;
    float c = g_cnt[v];
    g_invcnt[v] = (c > 0.0f) ? (1.0f / c) : 0.0f;
}

// ============================================================================
// 2) W_conv -> B-fragment layout (tf32-rounded)
// ============================================================================
__global__ void wfrag_kernel(const float* __restrict__ Wc) {
    int i = blockIdx.x * blockDim.x + threadIdx.x;   // (tap,ks,nt,lane)
    if (i >= 27 * 4 * 8 * 32) return;
    int lane = i & 31;
    int nt   = (i >> 5) & 7;
    int ks   = (i >> 8) & 3;
    int tap  = i >> 10;
    int ci = ks * 8 + (lane & 3);
    int co = nt * 8 + (lane >> 2);
    unsigned u0 = cvt_tf32(Wc[((size_t)tap * 32 + ci) * 64 + co]);
    unsigned u1 = cvt_tf32(Wc[((size_t)tap * 32 + ci + 4) * 64 + co]);
    g_wfrag[(size_t)i * 2 + 0] = __uint_as_float(u0);
    g_wfrag[(size_t)i * 2 + 1] = __uint_as_float(u1);
}

// ============================================================================
// 3) conv as implicit GEMM on tf32 mma.sync. Normalize = one FMUL by
//    g_invcnt during staging (no MUFU). Output stored fp16, occ-masked.
// ============================================================================
__global__ __launch_bounds__(256) void conv_kernel() {
    __shared__ unsigned pane[3 * PANE_ROWS * PANE_STRIDE];   // 28512 B

    const int x = blockIdx.x, y = blockIdx.y;
    const int tid  = threadIdx.x;
    const int lane = tid & 31;
    const int warp = tid >> 5;
    const int mw   = warp & 3;       // m-tile: z0w = 16*mw
    const int nh   = warp >> 2;      // n-half: co base = 32*nh
    const int z0w  = mw * 16;
    const int colbase = (x * G + y) * G;

    float acc[4][4];                 // [nt][frag]
#pragma unroll
    for (int nt = 0; nt < 4; nt++)
#pragma unroll
        for (int j = 0; j < 4; j++) acc[nt][j] = 0.0f;

    const float2* wfp = (const float2*)g_wfrag;

#pragma unroll 1
    for (int dx = 0; dx < 3; dx++) {
        __syncthreads();
        int gx = x + dx - 1;
        for (int i = tid; i < 3 * PANE_ROWS * 8; i += 256) {
            int c4  = i & 7;
            int row = (i >> 3) % PANE_ROWS;
            int p   = (i >> 3) / PANE_ROWS;
            int gy = y + p - 1;
            int gz = row - 1;
            float4 v = make_float4(0.f, 0.f, 0.f, 0.f);
            if ((unsigned)gx < G && (unsigned)gy < G && (unsigned)gz < G) {
                int vox = (gx * G + gy) * G + gz;
                v = *(const float4*)(g_voxsum + ((size_t)vox << 5) + c4 * 4);
                float inv = g_invcnt[vox];          // pure FMUL normalize
                v.x *= inv; v.y *= inv; v.z *= inv; v.w *= inv;
            }
            unsigned* dst = pane + (p * PANE_ROWS + row) * PANE_STRIDE + c4 * 4;
            dst[0] = cvt_tf32(v.x);
            dst[1] = cvt_tf32(v.y);
            dst[2] = cvt_tf32(v.z);
            dst[3] = cvt_tf32(v.w);
        }
        __syncthreads();

#pragma unroll 1
        for (int dy = 0; dy < 3; dy++) {
            const unsigned* pb = pane + dy * PANE_ROWS * PANE_STRIDE;
#pragma unroll 1
            for (int dz = 0; dz < 3; dz++) {
                int tap = (dx * 3 + dy) * 3 + dz;

                float2 bf[4][4];     // [ks][nt]
#pragma unroll
                for (int ks = 0; ks < 4; ks++)
#pragma unroll
                    for (int nt = 0; nt < 4; nt++)
                        bf[ks][nt] = wfp[((size_t)(tap * 4 + ks) * 8 + nh * 4 + nt) * 32 + lane];

#pragma unroll
                for (int ks = 0; ks < 4; ks++) {
                    int rowa = z0w + dz + (lane >> 2);
                    int cola = ks * 8 + (lane & 3);
                    const unsigned* ap = pb + rowa * PANE_STRIDE + cola;
                    unsigned a0 = ap[0];
                    unsigned a1 = ap[8 * PANE_STRIDE];
                    unsigned a2 = ap[4];
                    unsigned a3 = ap[8 * PANE_STRIDE + 4];
#pragma unroll
                    for (int nt = 0; nt < 4; nt++)
                        mma_tf32(acc[nt], a0, a1, a2, a3,
                                 __float_as_uint(bf[ks][nt].x),
                                 __float_as_uint(bf[ks][nt].y));
                }
            }
        }
    }

    int z1 = z0w + (lane >> 2);
    int z2 = z1 + 8;
    float occ1 = (g_invcnt[colbase + z1] > 0.0f) ? 1.0f : 0.0f;
    float occ2 = (g_invcnt[colbase + z2] > 0.0f) ? 1.0f : 0.0f;
#pragma unroll
    for (int nt = 0; nt < 4; nt++) {
        int co = nh * 32 + nt * 8 + (lane & 3) * 2;
        __half2 v1 = __floats2half2_rn(acc[nt][0] * occ1, acc[nt][1] * occ1);
        __half2 v2 = __floats2half2_rn(acc[nt][2] * occ2, acc[nt][3] * occ2);
        *(__half2*)(g_conv + (size_t)(colbase + z1) * OUTC + co) = v1;
        *(__half2*)(g_conv + (size_t)(colbase + z2) * OUTC + co) = v2;
    }
}

// ============================================================================
// 4a) residual linear as tf32 MMA (R10 measured: 93us)
// ============================================================================
__global__ __launch_bounds__(256) void residual_kernel(const float* __restrict__ feats,
                                                       const float* __restrict__ Wlin,
                                                       const float* __restrict__ blin,
                                                       float* __restrict__ out, int n) {
    __shared__ uint2 bsm[8 * 4 * 32];   // [nt][ks][lane]  8KB
    __shared__ float2 bbias[8 * 4];     // [nt][tig]

    const int tid  = threadIdx.x;
    const int lane = tid & 31;
    const int warp = tid >> 5;

    for (int i = tid; i < 8 * 4 * 32; i += 256) {
        int l  = i & 31;
        int ks = (i >> 5) & 3;
        int nt = i >> 7;
        int k = ks * 8 + (l & 3);
        int nn = nt * 8 + (l >> 2);
        uint2 b;
        b.x = cvt_tf32(Wlin[(size_t)nn * INC + k]);
        b.y = cvt_tf32(Wlin[(size_t)nn * INC + k + 4]);
        bsm[i] = b;
    }
    if (tid < 32) {
        int nt = tid >> 2, tig = tid & 3;
        bbias[nt * 4 + tig] = make_float2(blin[nt * 8 + 2 * tig], blin[nt * 8 + 2 * tig + 1]);
    }
    __syncthreads();

    const int gwarp  = blockIdx.x * 8 + warp;
    const int nwarps = gridDim.x * 8;
    const int ntiles = (n + 15) >> 4;
    const int gid = lane >> 2;         // 0..7
    const int tig = lane & 3;          // 0..3

    for (int tile = gwarp; tile < ntiles; tile += nwarps) {
        int p0 = tile * 16;
        int pr1 = p0 + gid;
        int pr2 = p0 + gid + 8;
        bool v1 = pr1 < n, v2 = pr2 < n;
        const float* f1 = feats + (size_t)pr1 * INC;
        const float* f2 = feats + (size_t)pr2 * INC;

        float acc[8][4];
#pragma unroll
        for (int nt = 0; nt < 8; nt++) {
            float2 bb = bbias[nt * 4 + tig];
            acc[nt][0] = bb.x; acc[nt][1] = bb.y;
            acc[nt][2] = bb.x; acc[nt][3] = bb.y;
        }

#pragma unroll
        for (int ks = 0; ks < 4; ks++) {
            int c = ks * 8 + tig;
            unsigned a0 = v1 ? cvt_tf32(f1[c])     : 0u;
            unsigned a1 = v2 ? cvt_tf32(f2[c])     : 0u;
            unsigned a2 = v1 ? cvt_tf32(f1[c + 4]) : 0u;
            unsigned a3 = v2 ? cvt_tf32(f2[c + 4]) : 0u;
#pragma unroll
            for (int nt = 0; nt < 8; nt++) {
                uint2 b = bsm[(nt * 4 + ks) * 32 + lane];
                mma_tf32(acc[nt], a0, a1, a2, a3, b.x, b.y);
            }
        }

        if (v1) {
            float2* o1 = (float2*)(out + (size_t)pr1 * OUTC);
#pragma unroll
            for (int nt = 0; nt < 8; nt++)
                o1[nt * 4 + tig] = make_float2(acc[nt][0], acc[nt][1]);
        }
        if (v2) {
            float2* o2 = (float2*)(out + (size_t)pr2 * OUTC);
#pragma unroll
            for (int nt = 0; nt < 8; nt++)
                o2[nt * 4 + tig] = make_float2(acc[nt][2], acc[nt][3]);
        }
    }
}

// ============================================================================
// 4b) trilinear devoxelize: fp16 gathers onto residual already in out
// ============================================================================
__global__ __launch_bounds__(256) void devox_kernel(const float* __restrict__ pts,
                                                    float* __restrict__ out, int n) {
    const int lane   = threadIdx.x & 31;
    const int warp   = (blockIdx.x * blockDim.x + threadIdx.x) >> 5;
    const int nwarps = (gridDim.x * blockDim.x) >> 5;

    for (int p = warp; p < n; p += nwarps) {
        float px = pts[3 * p + 0];
        float py = pts[3 * p + 1];
        float pz = pts[3 * p + 2];
        int bx = (int)floorf(px);
        int by = (int)floorf(py);
        int bz = (int)floorf(pz);
        float fx = px - (float)bx;
        float fy = py - (float)by;
        float fz = pz - (float)bz;

        float2* orow = (float2*)out + (size_t)p * (OUTC / 2);
        float2 acc = orow[lane];

#pragma unroll
        for (int c = 0; c < 8; c++) {
            int dx = (c >> 2) & 1, dy = (c >> 1) & 1, dz = c & 1;
            int nx = bx + dx, ny = by + dy, nz = bz + dz;
            float w = (dx ? fx : 1.0f - fx) * (dy ? fy : 1.0f - fy) * (dz ? fz : 1.0f - fz);
            if ((unsigned)nx < G && (unsigned)ny < G && (unsigned)nz < G) {
                int fl = (nx * G + ny) * G + nz;
                const __half2* row = (const __half2*)(g_conv + (size_t)fl * OUTC);
                float2 v = __half22float2(row[lane]);   // 64B/warp per corner
                acc.x += w * v.x;
                acc.y += w * v.y;
            }
        }

        orow[lane] = acc;
    }
}

// ============================================================================
extern "C" void kernel_launch(void* const* d_in, const int* in_sizes, int n_in,
                              void* d_out, int out_size) {
    const float* pts   = (const float*)d_in[0];
    const float* feats = (const float*)d_in[1];
    const float* Wc    = (const float*)d_in[2];
    const float* Wl    = (const float*)d_in[3];
    const float* bl    = (const float*)d_in[4];
    float* out = (float*)d_out;
    int npts = in_sizes[0] / 3;

    void *p_sum = nullptr, *p_cnt = nullptr;
    cudaGetSymbolAddress(&p_sum, g_voxsum);
    cudaGetSymbolAddress(&p_cnt, g_cnt);
    cudaMemsetAsync(p_sum, 0, (size_t)NVOX * INC * sizeof(float));
    cudaMemsetAsync(p_cnt, 0, (size_t)NVOX * sizeof(float));

    scatter_kernel<<<(npts + 255) / 256, 256>>>(pts, feats, npts);

    invcnt_kernel<<<NVOX / 256, 256>>>();

    wfrag_kernel<<<(27 * 4 * 8 * 32 + 255) / 256, 256>>>(Wc);

    dim3 cgrid(G, G);
    conv_kernel<<<cgrid, 256>>>();

    residual_kernel<<<2048, 256>>>(feats, Wl, bl, out, npts);

    devox_kernel<<<4096, 256>>>(pts, out, npts);
}

// round 12
// speedup vs baseline: 2.7416x; 1.1234x over previous
#include <cuda_runtime.h>
#include <cuda_fp16.h>
#include <cstdint>

#define G     64
#define NVOX  (G*G*G)
#define INC   32
#define OUTC  64
#define PANE_ROWS   66
#define PANE_STRIDE 36   // words; 36 mod 32 = 4 -> frag LDS bank-conflict-free

// ---- device scratch (allocation-free rule: static __device__ arrays) ----
__device__ float  g_voxsum[NVOX * INC];        // 32 MB: scatter sums (raw)
__device__ float  g_cnt[NVOX];                 //  1 MB: per-voxel point counts
__device__ float  g_invcnt[NVOX];              //  1 MB: cnt>0 ? 1/cnt : 0
__device__ __half g_conv[NVOX * OUTC];         // 32 MB: conv output (occ-masked, fp16)
__device__ float  g_wfrag[27 * 4 * 8 * 32 * 2]; // W_conv in mma B-fragment order (tf32)

__device__ __forceinline__ unsigned cvt_tf32(float f) {
    unsigned u;
    asm("cvt.rna.tf32.f32 %0, %1;" : "=r"(u) : "f"(f));
    return u;
}

__device__ __forceinline__ void mma_tf32(float c[4], unsigned a0, unsigned a1,
                                         unsigned a2, unsigned a3,
                                         unsigned b0, unsigned b1) {
    asm volatile(
        "mma.sync.aligned.m16n8k8.row.col.f32.tf32.tf32.f32 "
        "{%0,%1,%2,%3}, {%4,%5,%6,%7}, {%8,%9}, {%0,%1,%2,%3};"
        : "+f"(c[0]), "+f"(c[1]), "+f"(c[2]), "+f"(c[3])
        : "r"(a0), "r"(a1), "r"(a2), "r"(a3), "r"(b0), "r"(b1));
}

// ============================================================================
// 1) scatter-mean accumulate
// ============================================================================
__global__ void scatter_kernel(const float* __restrict__ pts,
                               const float* __restrict__ feats, int n) {
    int i = blockIdx.x * blockDim.x + threadIdx.x;
    if (i >= n) return;
    float px = pts[3 * i + 0];
    float py = pts[3 * i + 1];
    float pz = pts[3 * i + 2];
    int bx = (int)floorf(px);
    int by = (int)floorf(py);
    int bz = (int)floorf(pz);
    bx = min(max(bx, 0), G - 1);
    by = min(max(by, 0), G - 1);
    bz = min(max(bz, 0), G - 1);
    int fl = (bx * G + by) * G + bz;

    atomicAdd(&g_cnt[fl], 1.0f);

    const float4* f4 = (const float4*)(feats + (size_t)i * INC);
    float4* dst = (float4*)(g_voxsum + (size_t)fl * INC);
#pragma unroll
    for (int k = 0; k < INC / 4; k++) {
        float4 v = f4[k];
        atomicAdd(dst + k, v);
    }
}

// ============================================================================
// 1b) per-voxel inverse counts
// ============================================================================
__global__ void invcnt_kernel() {
    int v = blockIdx.x * blockDim.x + threadIdx.x;
    if (v >= NVOX) return;
    float c = g_cnt[v];
    g_invcnt[v] = (c > 0.0f) ? (1.0f / c) : 0.0f;
}

// ============================================================================
// 2) W_conv -> B-fragment layout (tf32-rounded)
// ============================================================================
__global__ void wfrag_kernel(const float* __restrict__ Wc) {
    int i = blockIdx.x * blockDim.x + threadIdx.x;   // (tap,ks,nt,lane)
    if (i >= 27 * 4 * 8 * 32) return;
    int lane = i & 31;
    int nt   = (i >> 5) & 7;
    int ks   = (i >> 8) & 3;
    int tap  = i >> 10;
    int ci = ks * 8 + (lane & 3);
    int co = nt * 8 + (lane >> 2);
    unsigned u0 = cvt_tf32(Wc[((size_t)tap * 32 + ci) * 64 + co]);
    unsigned u1 = cvt_tf32(Wc[((size_t)tap * 32 + ci + 4) * 64 + co]);
    g_wfrag[(size_t)i * 2 + 0] = __uint_as_float(u0);
    g_wfrag[(size_t)i * 2 + 1] = __uint_as_float(u1);
}

// ============================================================================
// 3) conv as implicit GEMM on tf32 mma.sync — 2-column CTA.
//    CTA = (x, y-pair): 4 staged y-panes serve both columns (-33% staging).
//    Warp tile M=32 (2 m-tiles) x N=32: B frags amortized over 2 m-tiles
//    (-33% L1 wavefronts per MMA). 8 warps = (col 2) x (mh 2) x (nh 2).
// ============================================================================
__global__ __launch_bounds__(256) void conv_kernel() {
    __shared__ unsigned pane[4 * PANE_ROWS * PANE_STRIDE];   // 38016 B

    const int x  = blockIdx.x;
    const int y0 = blockIdx.y * 2;
    const int tid  = threadIdx.x;
    const int lane = tid & 31;
    const int warp = tid >> 5;
    const int col  = warp & 1;          // which y column
    const int mh   = (warp >> 1) & 1;   // z half: 0 -> z 0..31, 1 -> z 32..63
    const int nh   = warp >> 2;         // co half
    const int z0w  = mh * 32;
    const int colbase = (x * G + y0 + col) * G;

    float acc[2][4][4];                 // [mt][nt][frag]
#pragma unroll
    for (int mt = 0; mt < 2; mt++)
#pragma unroll
        for (int nt = 0; nt < 4; nt++)
#pragma unroll
            for (int j = 0; j < 4; j++) acc[mt][nt][j] = 0.0f;

    const float2* wfp = (const float2*)g_wfrag;

#pragma unroll 1
    for (int dx = 0; dx < 3; dx++) {
        __syncthreads();
        int gx = x + dx - 1;
        // stage 4 y-panes (y0-1 .. y0+2) for this gx
        for (int i = tid; i < 4 * PANE_ROWS * 8; i += 256) {
            int c4  = i & 7;
            int row = (i >> 3) % PANE_ROWS;
            int p   = (i >> 3) / PANE_ROWS;
            int gy = y0 + p - 1;
            int gz = row - 1;
            float4 v = make_float4(0.f, 0.f, 0.f, 0.f);
            if ((unsigned)gx < G && (unsigned)gy < G && (unsigned)gz < G) {
                int vox = (gx * G + gy) * G + gz;
                v = *(const float4*)(g_voxsum + ((size_t)vox << 5) + c4 * 4);
                float inv = g_invcnt[vox];
                v.x *= inv; v.y *= inv; v.z *= inv; v.w *= inv;
            }
            unsigned* dst = pane + (p * PANE_ROWS + row) * PANE_STRIDE + c4 * 4;
            dst[0] = cvt_tf32(v.x);
            dst[1] = cvt_tf32(v.y);
            dst[2] = cvt_tf32(v.z);
            dst[3] = cvt_tf32(v.w);
        }
        __syncthreads();

#pragma unroll 1
        for (int dy = 0; dy < 3; dy++) {
            const unsigned* pb = pane + (col + dy) * PANE_ROWS * PANE_STRIDE;
#pragma unroll 1
            for (int dz = 0; dz < 3; dz++) {
                int tap = (dx * 3 + dy) * 3 + dz;
#pragma unroll
                for (int ks = 0; ks < 4; ks++) {
                    // B frags for this (tap, ks): 4 x LDG.64, reused by 2 m-tiles
                    float2 bf[4];
#pragma unroll
                    for (int nt = 0; nt < 4; nt++)
                        bf[nt] = wfp[((size_t)(tap * 4 + ks) * 8 + nh * 4 + nt) * 32 + lane];

                    int cola = ks * 8 + (lane & 3);
#pragma unroll
                    for (int mt = 0; mt < 2; mt++) {
                        int rowa = z0w + mt * 16 + dz + (lane >> 2);
                        const unsigned* ap = pb + rowa * PANE_STRIDE + cola;
                        unsigned a0 = ap[0];
                        unsigned a1 = ap[8 * PANE_STRIDE];
                        unsigned a2 = ap[4];
                        unsigned a3 = ap[8 * PANE_STRIDE + 4];
#pragma unroll
                        for (int nt = 0; nt < 4; nt++)
                            mma_tf32(acc[mt][nt], a0, a1, a2, a3,
                                     __float_as_uint(bf[nt].x),
                                     __float_as_uint(bf[nt].y));
                    }
                }
            }
        }
    }

#pragma unroll
    for (int mt = 0; mt < 2; mt++) {
        int z1 = z0w + mt * 16 + (lane >> 2);
        int z2 = z1 + 8;
        float occ1 = (g_invcnt[colbase + z1] > 0.0f) ? 1.0f : 0.0f;
        float occ2 = (g_invcnt[colbase + z2] > 0.0f) ? 1.0f : 0.0f;
#pragma unroll
        for (int nt = 0; nt < 4; nt++) {
            int co = nh * 32 + nt * 8 + (lane & 3) * 2;
            __half2 v1 = __floats2half2_rn(acc[mt][nt][0] * occ1, acc[mt][nt][1] * occ1);
            __half2 v2 = __floats2half2_rn(acc[mt][nt][2] * occ2, acc[mt][nt][3] * occ2);
            *(__half2*)(g_conv + (size_t)(colbase + z1) * OUTC + co) = v1;
            *(__half2*)(g_conv + (size_t)(colbase + z2) * OUTC + co) = v2;
        }
    }
}

// ============================================================================
// 4a) residual linear as tf32 MMA (R10 measured: 93us)
// ============================================================================
__global__ __launch_bounds__(256) void residual_kernel(const float* __restrict__ feats,
                                                       const float* __restrict__ Wlin,
                                                       const float* __restrict__ blin,
                                                       float* __restrict__ out, int n) {
    __shared__ uint2 bsm[8 * 4 * 32];   // [nt][ks][lane]  8KB
    __shared__ float2 bbias[8 * 4];     // [nt][tig]

    const int tid  = threadIdx.x;
    const int lane = tid & 31;
    const int warp = tid >> 5;

    for (int i = tid; i < 8 * 4 * 32; i += 256) {
        int l  = i & 31;
        int ks = (i >> 5) & 3;
        int nt = i >> 7;
        int k = ks * 8 + (l & 3);
        int nn = nt * 8 + (l >> 2);
        uint2 b;
        b.x = cvt_tf32(Wlin[(size_t)nn * INC + k]);
        b.y = cvt_tf32(Wlin[(size_t)nn * INC + k + 4]);
        bsm[i] = b;
    }
    if (tid < 32) {
        int nt = tid >> 2, tig = tid & 3;
        bbias[nt * 4 + tig] = make_float2(blin[nt * 8 + 2 * tig], blin[nt * 8 + 2 * tig + 1]);
    }
    __syncthreads();

    const int gwarp  = blockIdx.x * 8 + warp;
    const int nwarps = gridDim.x * 8;
    const int ntiles = (n + 15) >> 4;
    const int gid = lane >> 2;
    const int tig = lane & 3;

    for (int tile = gwarp; tile < ntiles; tile += nwarps) {
        int p0 = tile * 16;
        int pr1 = p0 + gid;
        int pr2 = p0 + gid + 8;
        bool v1 = pr1 < n, v2 = pr2 < n;
        const float* f1 = feats + (size_t)pr1 * INC;
        const float* f2 = feats + (size_t)pr2 * INC;

        float acc[8][4];
#pragma unroll
        for (int nt = 0; nt < 8; nt++) {
            float2 bb = bbias[nt * 4 + tig];
            acc[nt][0] = bb.x; acc[nt][1] = bb.y;
            acc[nt][2] = bb.x; acc[nt][3] = bb.y;
        }

#pragma unroll
        for (int ks = 0; ks < 4; ks++) {
            int c = ks * 8 + tig;
            unsigned a0 = v1 ? cvt_tf32(f1[c])     : 0u;
            unsigned a1 = v2 ? cvt_tf32(f2[c])     : 0u;
            unsigned a2 = v1 ? cvt_tf32(f1[c + 4]) : 0u;
            unsigned a3 = v2 ? cvt_tf32(f2[c + 4]) : 0u;
#pragma unroll
            for (int nt = 0; nt < 8; nt++) {
                uint2 b = bsm[(nt * 4 + ks) * 32 + lane];
                mma_tf32(acc[nt], a0, a1, a2, a3, b.x, b.y);
            }
        }

        if (v1) {
            float2* o1 = (float2*)(out + (size_t)pr1 * OUTC);
#pragma unroll
            for (int nt = 0; nt < 8; nt++)
                o1[nt * 4 + tig] = make_float2(acc[nt][0], acc[nt][1]);
        }
        if (v2) {
            float2* o2 = (float2*)(out + (size_t)pr2 * OUTC);
#pragma unroll
            for (int nt = 0; nt < 8; nt++)
                o2[nt * 4 + tig] = make_float2(acc[nt][2], acc[nt][3]);
        }
    }
}

// ============================================================================
// 4b) trilinear devoxelize: fp16 gathers onto residual already in out
// ============================================================================
__global__ __launch_bounds__(256) void devox_kernel(const float* __restrict__ pts,
                                                    float* __restrict__ out, int n) {
    const int lane   = threadIdx.x & 31;
    const int warp   = (blockIdx.x * blockDim.x + threadIdx.x) >> 5;
    const int nwarps = (gridDim.x * blockDim.x) >> 5;

    for (int p = warp; p < n; p += nwarps) {
        float px = pts[3 * p + 0];
        float py = pts[3 * p + 1];
        float pz = pts[3 * p + 2];
        int bx = (int)floorf(px);
        int by = (int)floorf(py);
        int bz = (int)floorf(pz);
        float fx = px - (float)bx;
        float fy = py - (float)by;
        float fz = pz - (float)bz;

        float2* orow = (float2*)out + (size_t)p * (OUTC / 2);
        float2 acc = orow[lane];

#pragma unroll
        for (int c = 0; c < 8; c++) {
            int dx = (c >> 2) & 1, dy = (c >> 1) & 1, dz = c & 1;
            int nx = bx + dx, ny = by + dy, nz = bz + dz;
            float w = (dx ? fx : 1.0f - fx) * (dy ? fy : 1.0f - fy) * (dz ? fz : 1.0f - fz);
            if ((unsigned)nx < G && (unsigned)ny < G && (unsigned)nz < G) {
                int fl = (nx * G + ny) * G + nz;
                const __half2* row = (const __half2*)(g_conv + (size_t)fl * OUTC);
                float2 v = __half22float2(row[lane]);
                acc.x += w * v.x;
                acc.y += w * v.y;
            }
        }

        orow[lane] = acc;
    }
}

// ============================================================================
extern "C" void kernel_launch(void* const* d_in, const int* in_sizes, int n_in,
                              void* d_out, int out_size) {
    const float* pts   = (const float*)d_in[0];
    const float* feats = (const float*)d_in[1];
    const float* Wc    = (const float*)d_in[2];
    const float* Wl    = (const float*)d_in[3];
    const float* bl    = (const float*)d_in[4];
    float* out = (float*)d_out;
    int npts = in_sizes[0] / 3;

    void *p_sum = nullptr, *p_cnt = nullptr;
    cudaGetSymbolAddress(&p_sum, g_voxsum);
    cudaGetSymbolAddress(&p_cnt, g_cnt);
    cudaMemsetAsync(p_sum, 0, (size_t)NVOX * INC * sizeof(float));
    cudaMemsetAsync(p_cnt, 0, (size_t)NVOX * sizeof(float));

    scatter_kernel<<<(npts + 255) / 256, 256>>>(pts, feats, npts);

    invcnt_kernel<<<NVOX / 256, 256>>>();

    wfrag_kernel<<<(27 * 4 * 8 * 32 + 255) / 256, 256>>>(Wc);

    dim3 cgrid(G, G / 2);
    conv_kernel<<<cgrid, 256>>>();

    residual_kernel<<<2048, 256>>>(feats, Wl, bl, out, npts);

    devox_kernel<<<4096, 256>>>(pts, out, npts);
}

// round 13
// speedup vs baseline: 3.0813x; 1.1239x over previous
#include <cuda_runtime.h>
#include <cuda_fp16.h>
#include <cstdint>

#define G     64
#define NVOX  (G*G*G)
#define INC   32
#define OUTC  64
#define PANE_ROWS   66
#define PANE_STRIDE 36   // words; 36 mod 32 = 4 -> frag LDS bank-conflict-free

// ---- device scratch (allocation-free rule: static __device__ arrays) ----
__device__ float  g_voxsum[NVOX * INC];        // 32 MB: scatter sums (raw)
__device__ float  g_cnt[NVOX];                 //  1 MB: per-voxel point counts
__device__ float  g_invcnt[NVOX];              //  1 MB: cnt>0 ? 1/cnt : 0
__device__ __half g_conv[NVOX * OUTC];         // 32 MB: conv output (occ-masked, fp16)
__device__ float  g_wfrag[27 * 4 * 8 * 32 * 2]; // W_conv in mma B-fragment order (tf32)

__device__ __forceinline__ unsigned cvt_tf32(float f) {
    unsigned u;
    asm("cvt.rna.tf32.f32 %0, %1;" : "=r"(u) : "f"(f));
    return u;
}

__device__ __forceinline__ void mma_tf32(float c[4], unsigned a0, unsigned a1,
                                         unsigned a2, unsigned a3,
                                         unsigned b0, unsigned b1) {
    asm volatile(
        "mma.sync.aligned.m16n8k8.row.col.f32.tf32.tf32.f32 "
        "{%0,%1,%2,%3}, {%4,%5,%6,%7}, {%8,%9}, {%0,%1,%2,%3};"
        : "+f"(c[0]), "+f"(c[1]), "+f"(c[2]), "+f"(c[3])
        : "r"(a0), "r"(a1), "r"(a2), "r"(a3), "r"(b0), "r"(b1));
}

// ============================================================================
// 1) scatter-mean accumulate
// ============================================================================
__global__ void scatter_kernel(const float* __restrict__ pts,
                               const float* __restrict__ feats, int n) {
    int i = blockIdx.x * blockDim.x + threadIdx.x;
    if (i >= n) return;
    float px = pts[3 * i + 0];
    float py = pts[3 * i + 1];
    float pz = pts[3 * i + 2];
    int bx = (int)floorf(px);
    int by = (int)floorf(py);
    int bz = (int)floorf(pz);
    bx = min(max(bx, 0), G - 1);
    by = min(max(by, 0), G - 1);
    bz = min(max(bz, 0), G - 1);
    int fl = (bx * G + by) * G + bz;

    atomicAdd(&g_cnt[fl], 1.0f);

    const float4* f4 = (const float4*)(feats + (size_t)i * INC);
    float4* dst = (float4*)(g_voxsum + (size_t)fl * INC);
#pragma unroll
    for (int k = 0; k < INC / 4; k++) {
        float4 v = f4[k];
        atomicAdd(dst + k, v);
    }
}

// ============================================================================
// 1b) per-voxel inverse counts
// ============================================================================
__global__ void invcnt_kernel() {
    int v = blockIdx.x * blockDim.x + threadIdx.x;
    if (v >= NVOX) return;
    float c = g_cnt[v];
    g_invcnt[v] = (c > 0.0f) ? (1.0f / c) : 0.0f;
}

// ============================================================================
// 2) W_conv -> B-fragment layout (tf32-rounded)
// ============================================================================
__global__ void wfrag_kernel(const float* __restrict__ Wc) {
    int i = blockIdx.x * blockDim.x + threadIdx.x;   // (tap,ks,nt,lane)
    if (i >= 27 * 4 * 8 * 32) return;
    int lane = i & 31;
    int nt   = (i >> 5) & 7;
    int ks   = (i >> 8) & 3;
    int tap  = i >> 10;
    int ci = ks * 8 + (lane & 3);
    int co = nt * 8 + (lane >> 2);
    unsigned u0 = cvt_tf32(Wc[((size_t)tap * 32 + ci) * 64 + co]);
    unsigned u1 = cvt_tf32(Wc[((size_t)tap * 32 + ci + 4) * 64 + co]);
    g_wfrag[(size_t)i * 2 + 0] = __uint_as_float(u0);
    g_wfrag[(size_t)i * 2 + 1] = __uint_as_float(u1);
}

// ============================================================================
// 3) conv as implicit GEMM on tf32 mma.sync — 2-column CTA (R12: 178us)
// ============================================================================
__global__ __launch_bounds__(256) void conv_kernel() {
    __shared__ unsigned pane[4 * PANE_ROWS * PANE_STRIDE];   // 38016 B

    const int x  = blockIdx.x;
    const int y0 = blockIdx.y * 2;
    const int tid  = threadIdx.x;
    const int lane = tid & 31;
    const int warp = tid >> 5;
    const int col  = warp & 1;
    const int mh   = (warp >> 1) & 1;
    const int nh   = warp >> 2;
    const int z0w  = mh * 32;
    const int colbase = (x * G + y0 + col) * G;

    float acc[2][4][4];
#pragma unroll
    for (int mt = 0; mt < 2; mt++)
#pragma unroll
        for (int nt = 0; nt < 4; nt++)
#pragma unroll
            for (int j = 0; j < 4; j++) acc[mt][nt][j] = 0.0f;

    const float2* wfp = (const float2*)g_wfrag;

#pragma unroll 1
    for (int dx = 0; dx < 3; dx++) {
        __syncthreads();
        int gx = x + dx - 1;
        for (int i = tid; i < 4 * PANE_ROWS * 8; i += 256) {
            int c4  = i & 7;
            int row = (i >> 3) % PANE_ROWS;
            int p   = (i >> 3) / PANE_ROWS;
            int gy = y0 + p - 1;
            int gz = row - 1;
            float4 v = make_float4(0.f, 0.f, 0.f, 0.f);
            if ((unsigned)gx < G && (unsigned)gy < G && (unsigned)gz < G) {
                int vox = (gx * G + gy) * G + gz;
                v = *(const float4*)(g_voxsum + ((size_t)vox << 5) + c4 * 4);
                float inv = g_invcnt[vox];
                v.x *= inv; v.y *= inv; v.z *= inv; v.w *= inv;
            }
            unsigned* dst = pane + (p * PANE_ROWS + row) * PANE_STRIDE + c4 * 4;
            dst[0] = cvt_tf32(v.x);
            dst[1] = cvt_tf32(v.y);
            dst[2] = cvt_tf32(v.z);
            dst[3] = cvt_tf32(v.w);
        }
        __syncthreads();

#pragma unroll 1
        for (int dy = 0; dy < 3; dy++) {
            const unsigned* pb = pane + (col + dy) * PANE_ROWS * PANE_STRIDE;
#pragma unroll 1
            for (int dz = 0; dz < 3; dz++) {
                int tap = (dx * 3 + dy) * 3 + dz;
#pragma unroll
                for (int ks = 0; ks < 4; ks++) {
                    float2 bf[4];
#pragma unroll
                    for (int nt = 0; nt < 4; nt++)
                        bf[nt] = wfp[((size_t)(tap * 4 + ks) * 8 + nh * 4 + nt) * 32 + lane];

                    int cola = ks * 8 + (lane & 3);
#pragma unroll
                    for (int mt = 0; mt < 2; mt++) {
                        int rowa = z0w + mt * 16 + dz + (lane >> 2);
                        const unsigned* ap = pb + rowa * PANE_STRIDE + cola;
                        unsigned a0 = ap[0];
                        unsigned a1 = ap[8 * PANE_STRIDE];
                        unsigned a2 = ap[4];
                        unsigned a3 = ap[8 * PANE_STRIDE + 4];
#pragma unroll
                        for (int nt = 0; nt < 4; nt++)
                            mma_tf32(acc[mt][nt], a0, a1, a2, a3,
                                     __float_as_uint(bf[nt].x),
                                     __float_as_uint(bf[nt].y));
                    }
                }
            }
        }
    }

#pragma unroll
    for (int mt = 0; mt < 2; mt++) {
        int z1 = z0w + mt * 16 + (lane >> 2);
        int z2 = z1 + 8;
        float occ1 = (g_invcnt[colbase + z1] > 0.0f) ? 1.0f : 0.0f;
        float occ2 = (g_invcnt[colbase + z2] > 0.0f) ? 1.0f : 0.0f;
#pragma unroll
        for (int nt = 0; nt < 4; nt++) {
            int co = nh * 32 + nt * 8 + (lane & 3) * 2;
            __half2 v1 = __floats2half2_rn(acc[mt][nt][0] * occ1, acc[mt][nt][1] * occ1);
            __half2 v2 = __floats2half2_rn(acc[mt][nt][2] * occ2, acc[mt][nt][3] * occ2);
            *(__half2*)(g_conv + (size_t)(colbase + z1) * OUTC + co) = v1;
            *(__half2*)(g_conv + (size_t)(colbase + z2) * OUTC + co) = v2;
        }
    }
}

// ============================================================================
// 4a) residual linear as tf32 MMA (R10 measured: 93us)
// ============================================================================
__global__ __launch_bounds__(256) void residual_kernel(const float* __restrict__ feats,
                                                       const float* __restrict__ Wlin,
                                                       const float* __restrict__ blin,
                                                       float* __restrict__ out, int n) {
    __shared__ uint2 bsm[8 * 4 * 32];   // [nt][ks][lane]  8KB
    __shared__ float2 bbias[8 * 4];     // [nt][tig]

    const int tid  = threadIdx.x;
    const int lane = tid & 31;
    const int warp = tid >> 5;

    for (int i = tid; i < 8 * 4 * 32; i += 256) {
        int l  = i & 31;
        int ks = (i >> 5) & 3;
        int nt = i >> 7;
        int k = ks * 8 + (l & 3);
        int nn = nt * 8 + (l >> 2);
        uint2 b;
        b.x = cvt_tf32(Wlin[(size_t)nn * INC + k]);
        b.y = cvt_tf32(Wlin[(size_t)nn * INC + k + 4]);
        bsm[i] = b;
    }
    if (tid < 32) {
        int nt = tid >> 2, tig = tid & 3;
        bbias[nt * 4 + tig] = make_float2(blin[nt * 8 + 2 * tig], blin[nt * 8 + 2 * tig + 1]);
    }
    __syncthreads();

    const int gwarp  = blockIdx.x * 8 + warp;
    const int nwarps = gridDim.x * 8;
    const int ntiles = (n + 15) >> 4;
    const int gid = lane >> 2;
    const int tig = lane & 3;

    for (int tile = gwarp; tile < ntiles; tile += nwarps) {
        int p0 = tile * 16;
        int pr1 = p0 + gid;
        int pr2 = p0 + gid + 8;
        bool v1 = pr1 < n, v2 = pr2 < n;
        const float* f1 = feats + (size_t)pr1 * INC;
        const float* f2 = feats + (size_t)pr2 * INC;

        float acc[8][4];
#pragma unroll
        for (int nt = 0; nt < 8; nt++) {
            float2 bb = bbias[nt * 4 + tig];
            acc[nt][0] = bb.x; acc[nt][1] = bb.y;
            acc[nt][2] = bb.x; acc[nt][3] = bb.y;
        }

#pragma unroll
        for (int ks = 0; ks < 4; ks++) {
            int c = ks * 8 + tig;
            unsigned a0 = v1 ? cvt_tf32(f1[c])     : 0u;
            unsigned a1 = v2 ? cvt_tf32(f2[c])     : 0u;
            unsigned a2 = v1 ? cvt_tf32(f1[c + 4]) : 0u;
            unsigned a3 = v2 ? cvt_tf32(f2[c + 4]) : 0u;
#pragma unroll
            for (int nt = 0; nt < 8; nt++) {
                uint2 b = bsm[(nt * 4 + ks) * 32 + lane];
                mma_tf32(acc[nt], a0, a1, a2, a3, b.x, b.y);
            }
        }

        if (v1) {
            float2* o1 = (float2*)(out + (size_t)pr1 * OUTC);
#pragma unroll
            for (int nt = 0; nt < 8; nt++)
                o1[nt * 4 + tig] = make_float2(acc[nt][0], acc[nt][1]);
        }
        if (v2) {
            float2* o2 = (float2*)(out + (size_t)pr2 * OUTC);
#pragma unroll
            for (int nt = 0; nt < 8; nt++)
                o2[nt * 4 + tig] = make_float2(acc[nt][2], acc[nt][3]);
        }
    }
}

// ============================================================================
// 4b) trilinear devoxelize: TWO points per warp, 16 lanes per point.
//     Lane owns 4 channels (uint2 = 2x half2): each corner gather is
//     16 lanes x 8B = 128B = ONE wavefront per point (was two).
// ============================================================================
__global__ __launch_bounds__(256) void devox_kernel(const float* __restrict__ pts,
                                                    float* __restrict__ out, int n) {
    const int lane   = threadIdx.x & 31;
    const int gwarp  = (blockIdx.x * blockDim.x + threadIdx.x) >> 5;
    const int nwarps = (gridDim.x * blockDim.x) >> 5;
    const int half   = lane >> 4;      // which point of the pair
    const int sl     = lane & 15;      // sub-lane: owns co 4*sl .. 4*sl+3

    for (int p0 = gwarp * 2; p0 < n; p0 += nwarps * 2) {
        int p = p0 + half;
        bool valid = p < n;
        int ps = valid ? p : (n - 1);  // safe clamped index for loads

        float px = pts[3 * ps + 0];
        float py = pts[3 * ps + 1];
        float pz = pts[3 * ps + 2];
        int bx = (int)floorf(px);
        int by = (int)floorf(py);
        int bz = (int)floorf(pz);
        float fx = px - (float)bx;
        float fy = py - (float)by;
        float fz = pz - (float)bz;

        float4* orow = (float4*)(out + (size_t)ps * OUTC);   // 16 float4 per row
        float4 acc = orow[sl];

#pragma unroll
        for (int c = 0; c < 8; c++) {
            int dx = (c >> 2) & 1, dy = (c >> 1) & 1, dz = c & 1;
            int nx = bx + dx, ny = by + dy, nz = bz + dz;
            float w = (dx ? fx : 1.0f - fx) * (dy ? fy : 1.0f - fy) * (dz ? fz : 1.0f - fz);
            if ((unsigned)nx < G && (unsigned)ny < G && (unsigned)nz < G) {
                int fl = (nx * G + ny) * G + nz;
                const uint2* row = (const uint2*)(g_conv + (size_t)fl * OUTC);
                uint2 v = row[sl];                        // 128B per 16-lane group
                float2 f0 = __half22float2(*(const __half2*)&v.x);
                float2 f1 = __half22float2(*(const __half2*)&v.y);
                acc.x += w * f0.x;
                acc.y += w * f0.y;
                acc.z += w * f1.x;
                acc.w += w * f1.y;
            }
        }

        if (valid) orow[sl] = acc;
    }
}

// ============================================================================
extern "C" void kernel_launch(void* const* d_in, const int* in_sizes, int n_in,
                              void* d_out, int out_size) {
    const float* pts   = (const float*)d_in[0];
    const float* feats = (const float*)d_in[1];
    const float* Wc    = (const float*)d_in[2];
    const float* Wl    = (const float*)d_in[3];
    const float* bl    = (const float*)d_in[4];
    float* out = (float*)d_out;
    int npts = in_sizes[0] / 3;

    void *p_sum = nullptr, *p_cnt = nullptr;
    cudaGetSymbolAddress(&p_sum, g_voxsum);
    cudaGetSymbolAddress(&p_cnt, g_cnt);
    cudaMemsetAsync(p_sum, 0, (size_t)NVOX * INC * sizeof(float));
    cudaMemsetAsync(p_cnt, 0, (size_t)NVOX * sizeof(float));

    scatter_kernel<<<(npts + 255) / 256, 256>>>(pts, feats, npts);

    invcnt_kernel<<<NVOX / 256, 256>>>();

    wfrag_kernel<<<(27 * 4 * 8 * 32 + 255) / 256, 256>>>(Wc);

    dim3 cgrid(G, G / 2);
    conv_kernel<<<cgrid, 256>>>();

    residual_kernel<<<2048, 256>>>(feats, Wl, bl, out, npts);

    devox_kernel<<<4096, 256>>>(pts, out, npts);
}